// round 2
// baseline (speedup 1.0000x reference)
#include <cuda_runtime.h>

#define Bv 8
#define Nv 256
#define Dv 128
#define Ev 32
#define Hv 4
#define HDv 32
#define BN (Bv*Nv)

// ---------------- scratch (device globals; no allocation allowed) ----------------
__device__ float g_wke[Dv*Ev];
__device__ float g_wve[Dv*Ev];
__device__ float g_ck[Dv];
__device__ float g_cv[Dv];
__device__ float g_q  [BN*Dv];
__device__ float g_kh [BN*Dv];
__device__ float g_vh [BN*Dv];
__device__ float g_qke[BN*Dv];          // [bn][h*32+e]
__device__ float g_S0 [Bv*Hv*Nv*Nv];    // [b][h][n][m]  q·k_h part of scores (unscaled)
__device__ float g_at [Bv*Hv*Nv*Nv];    // attention probs
__device__ float g_o1 [BN*Dv];          // attn @ v_h
__device__ float g_o2 [BN*Dv];          // wv_e @ ae
__device__ float g_hagg[BN*Dv];         // GCN aggregated features

// ---------------- K0: weight prep ----------------
__global__ void k_prep(const float* __restrict__ wk, const float* __restrict__ wv,
                       const float* __restrict__ edge_w, const float* __restrict__ edge_b,
                       const float* __restrict__ bk, const float* __restrict__ bv) {
    int t = threadIdx.x; // 256
    for (int idx = t; idx < Dv*Ev; idx += 256) {
        int d = idx >> 5, e = idx & 31;
        float sk = 0.f, sv = 0.f;
        for (int j = 0; j < Dv; j++) {
            float ew = edge_w[j*Ev + e];
            sk += wk[d*Dv + j] * ew;
            sv += wv[d*Dv + j] * ew;
        }
        g_wke[idx] = sk; g_wve[idx] = sv;
    }
    if (t < Dv) {
        float sk = bk[t], sv = bv[t];
        for (int j = 0; j < Dv; j++) {
            float eb = edge_b[j];
            sk += wk[t*Dv + j] * eb;
            sv += wv[t*Dv + j] * eb;
        }
        g_ck[t] = sk; g_cv[t] = sv;
    }
}

// ---------------- K1: projections q, k_h, v_h, qk_e ----------------
__global__ __launch_bounds__(128) void k_proj(const float* __restrict__ hin,
                                              const float* __restrict__ wq,
                                              const float* __restrict__ wk,
                                              const float* __restrict__ wv,
                                              const float* __restrict__ bq) {
    int bn = blockIdx.x, d = threadIdx.x;
    __shared__ float hs[Dv];
    __shared__ float qs[Dv];
    hs[d] = hin[(size_t)bn*Dv + d];
    __syncthreads();
    float aq = bq[d], ak = g_ck[d], av = g_cv[d];
    const float4* wq4 = (const float4*)wq;
    const float4* wk4 = (const float4*)wk;
    const float4* wv4 = (const float4*)wv;
    #pragma unroll 8
    for (int j4 = 0; j4 < Dv/4; j4++) {
        float h0 = hs[j4*4+0], h1 = hs[j4*4+1], h2 = hs[j4*4+2], h3 = hs[j4*4+3];
        float4 a = wq4[d*(Dv/4)+j4]; aq += a.x*h0 + a.y*h1 + a.z*h2 + a.w*h3;
        float4 b = wk4[d*(Dv/4)+j4]; ak += b.x*h0 + b.y*h1 + b.z*h2 + b.w*h3;
        float4 c = wv4[d*(Dv/4)+j4]; av += c.x*h0 + c.y*h1 + c.z*h2 + c.w*h3;
    }
    g_q [(size_t)bn*Dv + d] = aq;
    g_kh[(size_t)bn*Dv + d] = ak;
    g_vh[(size_t)bn*Dv + d] = av;
    qs[d] = aq;
    __syncthreads();
    int h0 = (d >> 5) << 5, e = d & 31;
    float s = 0.f;
    #pragma unroll
    for (int j = 0; j < HDv; j++) s += qs[h0+j] * g_wke[(h0+j)*Ev + e];
    g_qke[(size_t)bn*Dv + d] = s;
}

// ---------------- K2: GCN aggregation (16 query rows per CTA) ----------------
__global__ __launch_bounds__(128) void k_gcn(const float* __restrict__ hin,
                                             const float* __restrict__ adj) {
    int blk = blockIdx.x; int b = blk >> 4; int n0 = (blk & 15) << 4;
    __shared__ float adjs[16*Nv];
    __shared__ float degs[16];
    int t = threadIdx.x;
    for (int i = t; i < 16*Nv; i += 128) {
        int r = i >> 8, m = i & 255;
        adjs[i] = adj[((size_t)b*Nv + (n0+r))*Nv + m];
    }
    __syncthreads();
    if (t < 16) {
        adjs[t*Nv + n0 + t] += 1.0f;   // + eye self-loop
        float s = 0.f;
        for (int m = 0; m < Nv; m++) s += adjs[t*Nv + m];
        degs[t] = s;
    }
    __syncthreads();
    float acc[16];
    #pragma unroll
    for (int r = 0; r < 16; r++) acc[r] = 0.f;
    int d = t;
    for (int m = 0; m < Nv; m++) {
        float hv = hin[((size_t)b*Nv + m)*Dv + d];
        #pragma unroll
        for (int r = 0; r < 16; r++) acc[r] += adjs[r*Nv + m] * hv;
    }
    #pragma unroll
    for (int r = 0; r < 16; r++)
        g_hagg[((size_t)b*Nv + n0 + r)*Dv + d] = acc[r] / degs[r];
}

// ---------------- K3: S0 = Q_h K_h^T (register-tiled GEMM, K=32) ----------------
__global__ __launch_bounds__(256) void k_s0() {
    int bh = blockIdx.x; int b = bh >> 2, h = bh & 3;
    int n0 = blockIdx.y << 7, m0 = blockIdx.z << 7;
    __shared__ float Qt[128*33];
    __shared__ float Kt[128*33];
    int t = threadIdx.x;
    {
        int r = t >> 1, seg = (t & 1) << 4;
        const float* qsrc = g_q  + ((size_t)(b*Nv + n0 + r))*Dv + h*HDv + seg;
        const float* ksrc = g_kh + ((size_t)(b*Nv + m0 + r))*Dv + h*HDv + seg;
        #pragma unroll
        for (int i = 0; i < 4; i++) {
            float4 v = *(const float4*)(qsrc + i*4);
            float* p = &Qt[r*33 + seg + i*4];
            p[0]=v.x; p[1]=v.y; p[2]=v.z; p[3]=v.w;
            float4 w = *(const float4*)(ksrc + i*4);
            float* q = &Kt[r*33 + seg + i*4];
            q[0]=w.x; q[1]=w.y; q[2]=w.z; q[3]=w.w;
        }
    }
    __syncthreads();
    int tx = t & 15, ty = t >> 4;
    float acc[8][8];
    #pragma unroll
    for (int i = 0; i < 8; i++)
        #pragma unroll
        for (int j = 0; j < 8; j++) acc[i][j] = 0.f;
    for (int e = 0; e < HDv; e++) {
        float qr[8], kr[8];
        #pragma unroll
        for (int i = 0; i < 8; i++) { qr[i] = Qt[(ty*8+i)*33 + e]; kr[i] = Kt[(tx*8+i)*33 + e]; }
        #pragma unroll
        for (int i = 0; i < 8; i++)
            #pragma unroll
            for (int j = 0; j < 8; j++) acc[i][j] += qr[i]*kr[j];
    }
    float* dst = g_S0 + (size_t)(b*Hv + h)*Nv*Nv;
    #pragma unroll
    for (int i = 0; i < 8; i++) {
        int row = n0 + ty*8 + i;
        float* p = dst + (size_t)row*Nv + m0 + tx*8;
        float4 v0 = make_float4(acc[i][0],acc[i][1],acc[i][2],acc[i][3]);
        float4 v1 = make_float4(acc[i][4],acc[i][5],acc[i][6],acc[i][7]);
        *(float4*)p = v0; *(float4*)(p+4) = v1;
    }
}

// ---------------- K4: fused edge-scores + softmax + ae + o2 ----------------
__global__ __launch_bounds__(256) void k_att(const float* __restrict__ ef,
                                             const float* __restrict__ adj,
                                             const float* __restrict__ srcm) {
    int bn = blockIdx.x; int b = bn >> 8, n = bn & 255;
    __shared__ float efs[Nv*33];      // padded ef tile (conflict-free rows AND cols)
    __shared__ float qks[Dv];         // qk_e then reused as ae
    __shared__ float ats[Hv*Nv];      // scores -> attn
    __shared__ float red[Hv*Nv];      // reductions -> ae partials
    __shared__ float mxs[Hv], sms[Hv];
    int t = threadIdx.x;

    const float4* src = (const float4*)(ef + (size_t)bn*Nv*Ev);
    #pragma unroll
    for (int i = 0; i < 8; i++) {
        int idx4 = i*256 + t;
        float4 v = src[idx4];
        int fidx = idx4 << 2; int m = fidx >> 5; int e = fidx & 31;
        float* p = &efs[m*33 + e];
        p[0]=v.x; p[1]=v.y; p[2]=v.z; p[3]=v.w;
    }
    if (t < Dv) qks[t] = g_qke[(size_t)bn*Dv + t];
    __syncthreads();

    int m = t;
    float sc[Hv];
    {
        float s0[Hv];
        #pragma unroll
        for (int h = 0; h < Hv; h++)
            s0[h] = g_S0[((size_t)(b*Hv + h)*Nv + n)*Nv + m];
        float es[Hv] = {0.f,0.f,0.f,0.f};
        #pragma unroll 8
        for (int e = 0; e < Ev; e++) {
            float fv = efs[m*33 + e];
            #pragma unroll
            for (int h = 0; h < Hv; h++) es[h] += fv * qks[h*Ev + e];
        }
        float w = adj[(size_t)bn*Nv + m] * srcm[(size_t)bn*Nv + m];
        bool msk = (w == 0.0f);
        #pragma unroll
        for (int h = 0; h < Hv; h++)
            sc[h] = msk ? -1e30f : (s0[h] + es[h]) * 0.17677669529663687f; // 1/sqrt(32)
    }
    #pragma unroll
    for (int h = 0; h < Hv; h++) red[h*Nv + t] = sc[h];
    __syncthreads();
    for (int off = 128; off > 0; off >>= 1) {
        if (t < off) {
            #pragma unroll
            for (int h = 0; h < Hv; h++)
                red[h*Nv + t] = fmaxf(red[h*Nv + t], red[h*Nv + t + off]);
        }
        __syncthreads();
    }
    if (t < Hv) mxs[t] = red[t*Nv];
    __syncthreads();
    float ex[Hv];
    #pragma unroll
    for (int h = 0; h < Hv; h++) { ex[h] = __expf(sc[h] - mxs[h]); red[h*Nv + t] = ex[h]; }
    __syncthreads();
    for (int off = 128; off > 0; off >>= 1) {
        if (t < off) {
            #pragma unroll
            for (int h = 0; h < Hv; h++)
                red[h*Nv + t] += red[h*Nv + t + off];
        }
        __syncthreads();
    }
    if (t < Hv) sms[t] = red[t*Nv];
    __syncthreads();
    #pragma unroll
    for (int h = 0; h < Hv; h++) {
        float a = ex[h] / sms[h];
        ats[h*Nv + t] = a;
        g_at[((size_t)(b*Hv + h)*Nv + n)*Nv + m] = a;
    }
    __syncthreads();

    // ae[h][e] = sum_m attn[h][m]*ef[m][e]   (8 m-groups in parallel)
    {
        int e = t & 31, grp = t >> 5;
        float a0=0.f,a1=0.f,a2=0.f,a3=0.f;
        int mb = grp * 32;
        #pragma unroll 4
        for (int k = 0; k < 32; k++) {
            float fv = efs[(mb+k)*33 + e];
            a0 += ats[0*Nv + mb + k] * fv;
            a1 += ats[1*Nv + mb + k] * fv;
            a2 += ats[2*Nv + mb + k] * fv;
            a3 += ats[3*Nv + mb + k] * fv;
        }
        red[grp*128 + 0*32 + e] = a0;
        red[grp*128 + 1*32 + e] = a1;
        red[grp*128 + 2*32 + e] = a2;
        red[grp*128 + 3*32 + e] = a3;
    }
    __syncthreads();
    if (t < Dv) {
        float ae = 0.f;
        #pragma unroll
        for (int g = 0; g < 8; g++) ae += red[g*128 + t];
        qks[t] = ae;                  // ae layout [h*32+e]
    }
    __syncthreads();
    if (t < Dv) {
        int d = t, hh = d >> 5;
        float o2 = 0.f;
        #pragma unroll
        for (int e2 = 0; e2 < Ev; e2++) o2 += g_wve[d*Ev + e2] * qks[hh*Ev + e2];
        g_o2[(size_t)bn*Dv + d] = o2;
    }
}

// ---------------- K5: o1 = attn @ v_h (tiled GEMM, K=256) ----------------
__global__ __launch_bounds__(256) void k_o1() {
    int bh = blockIdx.x; int b = bh >> 2, h = bh & 3;
    int n0 = blockIdx.y << 6;
    __shared__ float At[64*33];
    __shared__ float Vt[32*33];
    int t = threadIdx.x, tx = t & 31, ty = t >> 5;
    float acc[8];
    #pragma unroll
    for (int i = 0; i < 8; i++) acc[i] = 0.f;
    const float* attn_base = g_at + ((size_t)(b*Hv + h)*Nv + n0)*Nv;
    for (int mc = 0; mc < Nv; mc += 32) {
        #pragma unroll
        for (int kk = 0; kk < 2; kk++) {
            int f = t*2 + kk;                  // 512 float4 = 64 rows x 8
            int row = f >> 3, c4 = f & 7;
            float4 v = *(const float4*)(attn_base + (size_t)row*Nv + mc + (c4<<2));
            float* p = &At[row*33 + (c4<<2)];
            p[0]=v.x; p[1]=v.y; p[2]=v.z; p[3]=v.w;
        }
        {
            int f = t; int row = f >> 3, c4 = f & 7;  // 256 float4 = 32 rows x 8
            float4 v = *(const float4*)(g_vh + (size_t)(b*Nv + mc + row)*Dv + h*HDv + (c4<<2));
            float* p = &Vt[row*33 + (c4<<2)];
            p[0]=v.x; p[1]=v.y; p[2]=v.z; p[3]=v.w;
        }
        __syncthreads();
        #pragma unroll 8
        for (int mm = 0; mm < 32; mm++) {
            float v = Vt[mm*33 + tx];
            #pragma unroll
            for (int i = 0; i < 8; i++) acc[i] += At[(ty*8+i)*33 + mm] * v;
        }
        __syncthreads();
    }
    #pragma unroll
    for (int i = 0; i < 8; i++)
        g_o1[(size_t)(b*Nv + n0 + ty*8 + i)*Dv + h*HDv + tx] = acc[i];
}

// ---------------- K6: out-proj + residual + layernorm + GCN proj + sum ----------------
__global__ __launch_bounds__(128) void k_final(const float* __restrict__ hin,
                                               const float* __restrict__ out_w,
                                               const float* __restrict__ out_b,
                                               const float* __restrict__ gcn_w,
                                               const float* __restrict__ gcn_b,
                                               const float* __restrict__ ln_g,
                                               const float* __restrict__ ln_b,
                                               float* __restrict__ out) {
    int bn = blockIdx.x, d = threadIdx.x;
    __shared__ float os[Dv];
    __shared__ float hag[Dv];
    __shared__ float rbuf[4];
    __shared__ float smu, srs;
    os[d]  = g_o1[(size_t)bn*Dv + d] + g_o2[(size_t)bn*Dv + d];
    hag[d] = g_hagg[(size_t)bn*Dv + d];
    __syncthreads();
    float y = out_b[d];
    {
        const float4* w4 = (const float4*)out_w;
        #pragma unroll 8
        for (int j4 = 0; j4 < Dv/4; j4++) {
            float4 w = w4[d*(Dv/4)+j4];
            y += w.x*os[j4*4] + w.y*os[j4*4+1] + w.z*os[j4*4+2] + w.w*os[j4*4+3];
        }
    }
    float x = hin[(size_t)bn*Dv + d] + y;
    float s = x;
    #pragma unroll
    for (int o = 16; o > 0; o >>= 1) s += __shfl_xor_sync(0xffffffff, s, o);
    if ((d & 31) == 0) rbuf[d >> 5] = s;
    __syncthreads();
    if (d == 0) smu = (rbuf[0]+rbuf[1]+rbuf[2]+rbuf[3]) * (1.0f/128.0f);
    __syncthreads();
    float xc = x - smu;
    float v2 = xc*xc;
    #pragma unroll
    for (int o = 16; o > 0; o >>= 1) v2 += __shfl_xor_sync(0xffffffff, v2, o);
    if ((d & 31) == 0) rbuf[d >> 5] = v2;
    __syncthreads();
    if (d == 0) {
        float var = (rbuf[0]+rbuf[1]+rbuf[2]+rbuf[3]) * (1.0f/128.0f);
        srs = rsqrtf(var + 1e-5f);
    }
    __syncthreads();
    float ha = ln_g[d]*xc*srs + ln_b[d];
    float g = gcn_b[d];
    {
        const float4* w4 = (const float4*)gcn_w;
        #pragma unroll 8
        for (int j4 = 0; j4 < Dv/4; j4++) {
            float4 w = w4[d*(Dv/4)+j4];
            g += w.x*hag[j4*4] + w.y*hag[j4*4+1] + w.z*hag[j4*4+2] + w.w*hag[j4*4+3];
        }
    }
    out[(size_t)bn*Dv + d] = g + ha;
}

extern "C" void kernel_launch(void* const* d_in, const int* in_sizes, int n_in,
                              void* d_out, int out_size) {
    const float* h     = (const float*)d_in[0];
    const float* adj   = (const float*)d_in[1];
    const float* ef    = (const float*)d_in[2];
    const float* smk   = (const float*)d_in[3];
    const float* gcn_w = (const float*)d_in[4];
    const float* gcn_b = (const float*)d_in[5];
    const float* edge_w= (const float*)d_in[6];
    const float* edge_b= (const float*)d_in[7];
    const float* wq    = (const float*)d_in[8];
    const float* wk    = (const float*)d_in[9];
    const float* wv    = (const float*)d_in[10];
    const float* bq    = (const float*)d_in[11];
    const float* bk    = (const float*)d_in[12];
    const float* bv    = (const float*)d_in[13];
    const float* out_w = (const float*)d_in[14];
    const float* out_b = (const float*)d_in[15];
    const float* ln_g  = (const float*)d_in[16];
    const float* ln_b  = (const float*)d_in[17];
    float* out = (float*)d_out;

    k_prep <<<1, 256>>>(wk, wv, edge_w, edge_b, bk, bv);
    k_proj <<<BN, 128>>>(h, wq, wk, wv, bq);
    k_gcn  <<<Bv*16, 128>>>(h, adj);
    k_s0   <<<dim3(Bv*Hv, 2, 2), 256>>>();
    k_att  <<<BN, 256>>>(ef, adj, smk);
    k_o1   <<<dim3(Bv*Hv, 4), 256>>>();
    k_final<<<BN, 128>>>(h, out_w, out_b, gcn_w, gcn_b, ln_g, ln_b, out);
}

// round 3
// speedup vs baseline: 2.0161x; 2.0161x over previous
#include <cuda_runtime.h>

#define Bv 8
#define Nv 256
#define Dv 128
#define Ev 32
#define Hv 4
#define HDv 32
#define BN (Bv*Nv)

// ---------------- scratch (device globals; no allocation allowed) ----------------
__device__ float g_wke[Dv*Ev];
__device__ float g_wve[Dv*Ev];
__device__ float g_ck[Dv];
__device__ float g_cv[Dv];
__device__ float g_q  [BN*Dv];
__device__ float g_kh [BN*Dv];
__device__ float g_vh [BN*Dv];
__device__ float g_qke[BN*Dv];          // [bn][h*32+e]
__device__ float g_S0 [Bv*Hv*Nv*Nv];    // [b][h][n][m]  q·k_h part of scores (unscaled)
__device__ float g_at [Bv*Hv*Nv*Nv];    // attention probs
__device__ float g_o1 [BN*Dv];          // attn @ v_h
__device__ float g_o2 [BN*Dv];          // wv_e @ ae
__device__ float g_hagg[BN*Dv];         // GCN aggregated features

// ---------------- K0: weight prep (parallel: 32 CTAs fold wk/wv@edge_w, 1 CTA consts) ----
__global__ __launch_bounds__(128) void k_prep(const float* __restrict__ wk,
                                              const float* __restrict__ wv,
                                              const float* __restrict__ edge_w,
                                              const float* __restrict__ edge_b,
                                              const float* __restrict__ bk,
                                              const float* __restrict__ bv) {
    int blk = blockIdx.x, t = threadIdx.x;
    if (blk < 32) {
        int dl = t >> 5, e = t & 31;
        int d = blk * 4 + dl;
        float sk = 0.f, sv = 0.f;
        #pragma unroll 8
        for (int j = 0; j < Dv; j++) {
            float ew = edge_w[j*Ev + e];
            sk += wk[d*Dv + j] * ew;
            sv += wv[d*Dv + j] * ew;
        }
        g_wke[d*Ev + e] = sk;
        g_wve[d*Ev + e] = sv;
    } else {
        // constants: ck = bk + wk@edge_b, cv = bv + wv@edge_b
        float sk = bk[t], sv = bv[t];
        #pragma unroll 8
        for (int j = 0; j < Dv; j++) {
            float eb = edge_b[j];
            sk += wk[t*Dv + j] * eb;
            sv += wv[t*Dv + j] * eb;
        }
        g_ck[t] = sk; g_cv[t] = sv;
    }
}

// ---------------- K1: projections q, k_h, v_h, qk_e ----------------
__global__ __launch_bounds__(128) void k_proj(const float* __restrict__ hin,
                                              const float* __restrict__ wq,
                                              const float* __restrict__ wk,
                                              const float* __restrict__ wv,
                                              const float* __restrict__ bq) {
    int bn = blockIdx.x, d = threadIdx.x;
    __shared__ float hs[Dv];
    __shared__ float qs[Dv];
    hs[d] = hin[(size_t)bn*Dv + d];
    __syncthreads();
    float aq = bq[d], ak = g_ck[d], av = g_cv[d];
    const float4* wq4 = (const float4*)wq;
    const float4* wk4 = (const float4*)wk;
    const float4* wv4 = (const float4*)wv;
    #pragma unroll 8
    for (int j4 = 0; j4 < Dv/4; j4++) {
        float h0 = hs[j4*4+0], h1 = hs[j4*4+1], h2 = hs[j4*4+2], h3 = hs[j4*4+3];
        float4 a = wq4[d*(Dv/4)+j4]; aq += a.x*h0 + a.y*h1 + a.z*h2 + a.w*h3;
        float4 b = wk4[d*(Dv/4)+j4]; ak += b.x*h0 + b.y*h1 + b.z*h2 + b.w*h3;
        float4 c = wv4[d*(Dv/4)+j4]; av += c.x*h0 + c.y*h1 + c.z*h2 + c.w*h3;
    }
    g_q [(size_t)bn*Dv + d] = aq;
    g_kh[(size_t)bn*Dv + d] = ak;
    g_vh[(size_t)bn*Dv + d] = av;
    qs[d] = aq;
    __syncthreads();
    int h0 = (d >> 5) << 5, e = d & 31;
    float s = 0.f;
    #pragma unroll
    for (int j = 0; j < HDv; j++) s += qs[h0+j] * g_wke[(h0+j)*Ev + e];
    g_qke[(size_t)bn*Dv + d] = s;
}

// ---------------- K2: GCN aggregation (8 query rows per CTA, grid 256) ----------------
__global__ __launch_bounds__(128) void k_gcn(const float* __restrict__ hin,
                                             const float* __restrict__ adj) {
    int blk = blockIdx.x; int b = blk >> 5; int n0 = (blk & 31) << 3;
    __shared__ float adjs[8*Nv];
    __shared__ float degs[8];
    int t = threadIdx.x;
    #pragma unroll
    for (int i = 0; i < 16; i++) {
        int idx = i*128 + t;
        int r = idx >> 8, m = idx & 255;
        adjs[idx] = adj[((size_t)b*Nv + (n0+r))*Nv + m];
    }
    __syncthreads();
    if (t < 8) adjs[t*Nv + n0 + t] += 1.0f;   // + eye self-loop
    __syncthreads();
    {
        // degree: 8 rows x 16 lanes, each lane sums 16 entries, shuffle-reduce width 16
        int r = t >> 4, lane = t & 15;
        float p = 0.f;
        #pragma unroll
        for (int k = 0; k < 16; k++) p += adjs[r*Nv + lane*16 + k];
        #pragma unroll
        for (int o = 8; o > 0; o >>= 1) p += __shfl_xor_sync(0xffffffffu, p, o, 16);
        if (lane == 0) degs[r] = p;
    }
    __syncthreads();
    float acc[8];
    #pragma unroll
    for (int r = 0; r < 8; r++) acc[r] = 0.f;
    int d = t;
    for (int m = 0; m < Nv; m++) {
        float hv = hin[((size_t)b*Nv + m)*Dv + d];
        #pragma unroll
        for (int r = 0; r < 8; r++) acc[r] += adjs[r*Nv + m] * hv;
    }
    #pragma unroll
    for (int r = 0; r < 8; r++)
        g_hagg[((size_t)b*Nv + n0 + r)*Dv + d] = acc[r] / degs[r];
}

// ---------------- K3: S0 = Q_h K_h^T (64x64 tiles, grid 512) ----------------
__global__ __launch_bounds__(256) void k_s0() {
    int bh = blockIdx.x; int b = bh >> 2, h = bh & 3;
    int n0 = blockIdx.y << 6, m0 = blockIdx.z << 6;
    __shared__ float Qt[64*33];
    __shared__ float Kt[64*33];
    int t = threadIdx.x;
    #pragma unroll
    for (int i = 0; i < 2; i++) {
        int f = i*256 + t;                 // 512 float4 = 64 rows x 8
        int r = f >> 3, c4 = (f & 7) << 2;
        float4 v = *(const float4*)(g_q  + ((size_t)(b*Nv + n0 + r))*Dv + h*HDv + c4);
        float* p = &Qt[r*33 + c4];
        p[0]=v.x; p[1]=v.y; p[2]=v.z; p[3]=v.w;
        float4 w = *(const float4*)(g_kh + ((size_t)(b*Nv + m0 + r))*Dv + h*HDv + c4);
        float* q = &Kt[r*33 + c4];
        q[0]=w.x; q[1]=w.y; q[2]=w.z; q[3]=w.w;
    }
    __syncthreads();
    int tx = t & 15, ty = t >> 4;          // 16x16 threads, 4x4 each
    float acc[4][4];
    #pragma unroll
    for (int i = 0; i < 4; i++)
        #pragma unroll
        for (int j = 0; j < 4; j++) acc[i][j] = 0.f;
    #pragma unroll 4
    for (int e = 0; e < HDv; e++) {
        float qr[4], kr[4];
        #pragma unroll
        for (int i = 0; i < 4; i++) { qr[i] = Qt[(ty*4+i)*33 + e]; kr[i] = Kt[(tx*4+i)*33 + e]; }
        #pragma unroll
        for (int i = 0; i < 4; i++)
            #pragma unroll
            for (int j = 0; j < 4; j++) acc[i][j] += qr[i]*kr[j];
    }
    float* dst = g_S0 + (size_t)(b*Hv + h)*Nv*Nv;
    #pragma unroll
    for (int i = 0; i < 4; i++) {
        float* p = dst + (size_t)(n0 + ty*4 + i)*Nv + m0 + tx*4;
        *(float4*)p = make_float4(acc[i][0],acc[i][1],acc[i][2],acc[i][3]);
    }
}

// ---------------- K4: fused edge-scores + softmax + ae + o2 (shuffle reductions) -----
__global__ __launch_bounds__(256) void k_att(const float* __restrict__ ef,
                                             const float* __restrict__ adj,
                                             const float* __restrict__ srcm) {
    int bn = blockIdx.x; int b = bn >> 8, n = bn & 255;
    __shared__ float efs[Nv*33];      // padded ef tile (conflict-free rows AND cols)
    __shared__ float qks[Dv];         // qk_e, later reused as ae
    __shared__ float ats[Hv*Nv];      // attn probs
    __shared__ float red[Hv*Nv];      // ae partials (8 groups x 128)
    __shared__ float wred[32];
    __shared__ float mxs[Hv], sms[Hv];
    int t = threadIdx.x, lane = t & 31, wid = t >> 5;
    int m = t;

    // front-issue all global loads
    float4 v[8];
    const float4* src = (const float4*)(ef + (size_t)bn*Nv*Ev);
    #pragma unroll
    for (int i = 0; i < 8; i++) v[i] = src[i*256 + t];
    float s0[Hv];
    #pragma unroll
    for (int h = 0; h < Hv; h++)
        s0[h] = g_S0[((size_t)(b*Hv + h)*Nv + n)*Nv + m];
    float w = adj[(size_t)bn*Nv + m] * srcm[(size_t)bn*Nv + m];
    if (t < Dv) qks[t] = g_qke[(size_t)bn*Dv + t];
    #pragma unroll
    for (int i = 0; i < 8; i++) {
        int fidx = (i*256 + t) << 2; int mm = fidx >> 5; int e = fidx & 31;
        float* p = &efs[mm*33 + e];
        p[0]=v[i].x; p[1]=v[i].y; p[2]=v[i].z; p[3]=v[i].w;
    }
    __syncthreads();

    float sc[Hv];
    {
        float es[Hv] = {0.f,0.f,0.f,0.f};
        #pragma unroll 8
        for (int e = 0; e < Ev; e++) {
            float fv = efs[m*33 + e];
            #pragma unroll
            for (int h = 0; h < Hv; h++) es[h] += fv * qks[h*Ev + e];
        }
        bool msk = (w == 0.0f);
        #pragma unroll
        for (int h = 0; h < Hv; h++)
            sc[h] = msk ? -1e30f : (s0[h] + es[h]) * 0.17677669529663687f; // 1/sqrt(32)
    }

    // max: warp shuffle + 1 cross-warp step
    {
        float wm[Hv];
        #pragma unroll
        for (int h = 0; h < Hv; h++) {
            wm[h] = sc[h];
            #pragma unroll
            for (int o = 16; o > 0; o >>= 1)
                wm[h] = fmaxf(wm[h], __shfl_xor_sync(0xffffffffu, wm[h], o));
        }
        if (lane == 0) {
            #pragma unroll
            for (int h = 0; h < Hv; h++) wred[h*8 + wid] = wm[h];
        }
    }
    __syncthreads();
    if (t < 32) {
        float val = wred[t];   // t = h*8 + w
        val = fmaxf(val, __shfl_xor_sync(0xffffffffu, val, 1));
        val = fmaxf(val, __shfl_xor_sync(0xffffffffu, val, 2));
        val = fmaxf(val, __shfl_xor_sync(0xffffffffu, val, 4));
        if ((t & 7) == 0) mxs[t >> 3] = val;
    }
    __syncthreads();

    float ex[Hv];
    {
        float ws[Hv];
        #pragma unroll
        for (int h = 0; h < Hv; h++) {
            ex[h] = __expf(sc[h] - mxs[h]);
            ws[h] = ex[h];
            #pragma unroll
            for (int o = 16; o > 0; o >>= 1)
                ws[h] += __shfl_xor_sync(0xffffffffu, ws[h], o);
        }
        if (lane == 0) {
            #pragma unroll
            for (int h = 0; h < Hv; h++) wred[h*8 + wid] = ws[h];
        }
    }
    __syncthreads();
    if (t < 32) {
        float val = wred[t];
        val += __shfl_xor_sync(0xffffffffu, val, 1);
        val += __shfl_xor_sync(0xffffffffu, val, 2);
        val += __shfl_xor_sync(0xffffffffu, val, 4);
        if ((t & 7) == 0) sms[t >> 3] = val;
    }
    __syncthreads();

    #pragma unroll
    for (int h = 0; h < Hv; h++) {
        float a = ex[h] / sms[h];
        ats[h*Nv + t] = a;
        g_at[((size_t)(b*Hv + h)*Nv + n)*Nv + m] = a;
    }
    __syncthreads();

    // ae[h][e] = sum_m attn[h][m]*ef[m][e]   (8 m-groups in parallel)
    {
        int e = t & 31, grp = t >> 5;
        float a0=0.f,a1=0.f,a2=0.f,a3=0.f;
        int mb = grp * 32;
        #pragma unroll 4
        for (int k = 0; k < 32; k++) {
            float fv = efs[(mb+k)*33 + e];
            a0 += ats[0*Nv + mb + k] * fv;
            a1 += ats[1*Nv + mb + k] * fv;
            a2 += ats[2*Nv + mb + k] * fv;
            a3 += ats[3*Nv + mb + k] * fv;
        }
        red[grp*128 + 0*32 + e] = a0;
        red[grp*128 + 1*32 + e] = a1;
        red[grp*128 + 2*32 + e] = a2;
        red[grp*128 + 3*32 + e] = a3;
    }
    __syncthreads();
    if (t < Dv) {
        float ae = 0.f;
        #pragma unroll
        for (int g = 0; g < 8; g++) ae += red[g*128 + t];
        qks[t] = ae;                  // ae layout [h*32+e]
    }
    __syncthreads();
    if (t < Dv) {
        int d = t, hh = d >> 5;
        float o2 = 0.f;
        #pragma unroll
        for (int e2 = 0; e2 < Ev; e2++) o2 += g_wve[d*Ev + e2] * qks[hh*Ev + e2];
        g_o2[(size_t)bn*Dv + d] = o2;
    }
}

// ---------------- K5: o1 = attn @ v_h (32-row tiles, grid 256) ----------------
__global__ __launch_bounds__(256) void k_o1() {
    int bh = blockIdx.x; int b = bh >> 2, h = bh & 3;
    int n0 = blockIdx.y << 5;
    __shared__ float At[32*33];
    __shared__ float Vt[32*33];
    int t = threadIdx.x, tx = t & 31, ty = t >> 5;
    float acc[4];
    #pragma unroll
    for (int i = 0; i < 4; i++) acc[i] = 0.f;
    const float* attn_base = g_at + ((size_t)(b*Hv + h)*Nv + n0)*Nv;
    for (int mc = 0; mc < Nv; mc += 32) {
        {
            int row = t >> 3, c4 = (t & 7) << 2;   // 256 float4 = 32 rows x 8
            float4 va = *(const float4*)(attn_base + (size_t)row*Nv + mc + c4);
            float* p = &At[row*33 + c4];
            p[0]=va.x; p[1]=va.y; p[2]=va.z; p[3]=va.w;
            float4 vv = *(const float4*)(g_vh + (size_t)(b*Nv + mc + row)*Dv + h*HDv + c4);
            float* q = &Vt[row*33 + c4];
            q[0]=vv.x; q[1]=vv.y; q[2]=vv.z; q[3]=vv.w;
        }
        __syncthreads();
        #pragma unroll 8
        for (int mm = 0; mm < 32; mm++) {
            float vv = Vt[mm*33 + tx];
            #pragma unroll
            for (int i = 0; i < 4; i++) acc[i] += At[(ty*4+i)*33 + mm] * vv;
        }
        __syncthreads();
    }
    #pragma unroll
    for (int i = 0; i < 4; i++)
        g_o1[(size_t)(b*Nv + n0 + ty*4 + i)*Dv + h*HDv + tx] = acc[i];
}

// ---------------- K6: out-proj + residual + layernorm + GCN proj + sum ----------------
__global__ __launch_bounds__(128) void k_final(const float* __restrict__ hin,
                                               const float* __restrict__ out_w,
                                               const float* __restrict__ out_b,
                                               const float* __restrict__ gcn_w,
                                               const float* __restrict__ gcn_b,
                                               const float* __restrict__ ln_g,
                                               const float* __restrict__ ln_b,
                                               float* __restrict__ out) {
    int bn = blockIdx.x, d = threadIdx.x;
    __shared__ float os[Dv];
    __shared__ float hag[Dv];
    __shared__ float rbuf[4];
    __shared__ float smu, srs;
    os[d]  = g_o1[(size_t)bn*Dv + d] + g_o2[(size_t)bn*Dv + d];
    hag[d] = g_hagg[(size_t)bn*Dv + d];
    __syncthreads();
    float y = out_b[d];
    {
        const float4* w4 = (const float4*)out_w;
        #pragma unroll 8
        for (int j4 = 0; j4 < Dv/4; j4++) {
            float4 w = w4[d*(Dv/4)+j4];
            y += w.x*os[j4*4] + w.y*os[j4*4+1] + w.z*os[j4*4+2] + w.w*os[j4*4+3];
        }
    }
    float x = hin[(size_t)bn*Dv + d] + y;
    float s = x;
    #pragma unroll
    for (int o = 16; o > 0; o >>= 1) s += __shfl_xor_sync(0xffffffffu, s, o);
    if ((d & 31) == 0) rbuf[d >> 5] = s;
    __syncthreads();
    if (d == 0) smu = (rbuf[0]+rbuf[1]+rbuf[2]+rbuf[3]) * (1.0f/128.0f);
    __syncthreads();
    float xc = x - smu;
    float v2 = xc*xc;
    #pragma unroll
    for (int o = 16; o > 0; o >>= 1) v2 += __shfl_xor_sync(0xffffffffu, v2, o);
    if ((d & 31) == 0) rbuf[d >> 5] = v2;
    __syncthreads();
    if (d == 0) {
        float var = (rbuf[0]+rbuf[1]+rbuf[2]+rbuf[3]) * (1.0f/128.0f);
        srs = rsqrtf(var + 1e-5f);
    }
    __syncthreads();
    float ha = ln_g[d]*xc*srs + ln_b[d];
    float g = gcn_b[d];
    {
        const float4* w4 = (const float4*)gcn_w;
        #pragma unroll 8
        for (int j4 = 0; j4 < Dv/4; j4++) {
            float4 w = w4[d*(Dv/4)+j4];
            g += w.x*hag[j4*4] + w.y*hag[j4*4+1] + w.z*hag[j4*4+2] + w.w*hag[j4*4+3];
        }
    }
    out[(size_t)bn*Dv + d] = g + ha;
}

extern "C" void kernel_launch(void* const* d_in, const int* in_sizes, int n_in,
                              void* d_out, int out_size) {
    const float* h     = (const float*)d_in[0];
    const float* adj   = (const float*)d_in[1];
    const float* ef    = (const float*)d_in[2];
    const float* smk   = (const float*)d_in[3];
    const float* gcn_w = (const float*)d_in[4];
    const float* gcn_b = (const float*)d_in[5];
    const float* edge_w= (const float*)d_in[6];
    const float* edge_b= (const float*)d_in[7];
    const float* wq    = (const float*)d_in[8];
    const float* wk    = (const float*)d_in[9];
    const float* wv    = (const float*)d_in[10];
    const float* bq    = (const float*)d_in[11];
    const float* bk    = (const float*)d_in[12];
    const float* bv    = (const float*)d_in[13];
    const float* out_w = (const float*)d_in[14];
    const float* out_b = (const float*)d_in[15];
    const float* ln_g  = (const float*)d_in[16];
    const float* ln_b  = (const float*)d_in[17];
    float* out = (float*)d_out;

    k_prep <<<33, 128>>>(wk, wv, edge_w, edge_b, bk, bv);
    k_proj <<<BN, 128>>>(h, wq, wk, wv, bq);
    k_gcn  <<<Bv*32, 128>>>(h, adj);
    k_s0   <<<dim3(Bv*Hv, 4, 4), 256>>>();
    k_att  <<<BN, 256>>>(ef, adj, smk);
    k_o1   <<<dim3(Bv*Hv, 8), 256>>>();
    k_final<<<BN, 128>>>(h, out_w, out_b, gcn_w, gcn_b, ln_g, ln_b, out);
}

// round 4
// speedup vs baseline: 3.8571x; 1.9132x over previous
#include <cuda_runtime.h>

#define Bv 8
#define Nv 256
#define Dv 128
#define Ev 32
#define Hv 4
#define HDv 32
#define BN (Bv*Nv)

// ---------------- scratch (device globals; no allocation allowed) ----------------
__device__ float g_wke[Dv*Ev];
__device__ float g_wve[Dv*Ev];
__device__ float g_ck[Dv];
__device__ float g_cv[Dv];
__device__ float g_q  [BN*Dv];
__device__ float g_kh [BN*Dv];
__device__ float g_vh [BN*Dv];
__device__ float g_qke[BN*Dv];          // [bn][h*32+e]
__device__ float g_S0 [Bv*Hv*Nv*Nv];    // [b][h][n][m]  q·k_h part of scores (unscaled)
__device__ float g_at [Bv*Hv*Nv*Nv];    // attention probs
__device__ float g_o1 [BN*Dv];          // attn @ v_h
__device__ float g_o2 [BN*Dv];          // wv_e @ ae
__device__ float g_hagg[BN*Dv];         // GCN aggregated features

// ---------------- K0: weight prep (parallel) ----------------
__global__ __launch_bounds__(128) void k_prep(const float* __restrict__ wk,
                                              const float* __restrict__ wv,
                                              const float* __restrict__ edge_w,
                                              const float* __restrict__ edge_b,
                                              const float* __restrict__ bk,
                                              const float* __restrict__ bv) {
    int blk = blockIdx.x, t = threadIdx.x;
    if (blk < 32) {
        int dl = t >> 5, e = t & 31;
        int d = blk * 4 + dl;
        float sk = 0.f, sv = 0.f;
        #pragma unroll 8
        for (int j = 0; j < Dv; j++) {
            float ew = edge_w[j*Ev + e];
            sk += wk[d*Dv + j] * ew;
            sv += wv[d*Dv + j] * ew;
        }
        g_wke[d*Ev + e] = sk;
        g_wve[d*Ev + e] = sv;
    } else {
        float sk = bk[t], sv = bv[t];
        #pragma unroll 8
        for (int j = 0; j < Dv; j++) {
            float eb = edge_b[j];
            sk += wk[t*Dv + j] * eb;
            sv += wv[t*Dv + j] * eb;
        }
        g_ck[t] = sk; g_cv[t] = sv;
    }
}

// ---------------- K1: projections, 16 rows/CTA, weights amortized ----------------
__global__ __launch_bounds__(384) void k_proj(const float* __restrict__ hin,
                                              const float* __restrict__ wq,
                                              const float* __restrict__ wk,
                                              const float* __restrict__ wv,
                                              const float* __restrict__ bq) {
    int bn0 = blockIdx.x << 4;
    int t = threadIdx.x;
    __shared__ float hs[16*Dv];
    __shared__ float qs[16*Dv];
    for (int i = t; i < 16*Dv; i += 384)
        hs[i] = hin[(size_t)bn0*Dv + i];
    __syncthreads();
    int mat = t >> 7, d = t & 127;
    const float* W = (mat == 0) ? wq : (mat == 1) ? wk : wv;
    float bias = (mat == 0) ? bq[d] : (mat == 1) ? g_ck[d] : g_cv[d];
    float acc[16];
    #pragma unroll
    for (int r = 0; r < 16; r++) acc[r] = bias;
    const float4* W4 = (const float4*)W;
    const float4* hs4 = (const float4*)hs;
    #pragma unroll 4
    for (int j4 = 0; j4 < 32; j4++) {
        float4 w = W4[d*32 + j4];
        #pragma unroll
        for (int r = 0; r < 16; r++) {
            float4 hv = hs4[r*32 + j4];
            acc[r] += w.x*hv.x + w.y*hv.y + w.z*hv.z + w.w*hv.w;
        }
    }
    float* dst = (mat == 0) ? g_q : (mat == 1) ? g_kh : g_vh;
    #pragma unroll
    for (int r = 0; r < 16; r++) dst[(size_t)(bn0 + r)*Dv + d] = acc[r];
    if (mat == 0) {
        #pragma unroll
        for (int r = 0; r < 16; r++) qs[r*Dv + d] = acc[r];
    }
    __syncthreads();
    if (t < Dv) {
        int hh = (d >> 5) << 5, e = d & 31;
        float we[32];
        #pragma unroll
        for (int j = 0; j < 32; j++) we[j] = g_wke[(hh + j)*Ev + e];
        #pragma unroll 2
        for (int r = 0; r < 16; r++) {
            float s = 0.f;
            #pragma unroll 8
            for (int j = 0; j < 32; j++) s += qs[r*Dv + hh + j] * we[j];
            g_qke[(size_t)(bn0 + r)*Dv + d] = s;
        }
    }
}

// ---------------- K2: GCN aggregation (8 query rows per CTA, grid 256) ----------------
__global__ __launch_bounds__(128) void k_gcn(const float* __restrict__ hin,
                                             const float* __restrict__ adj) {
    int blk = blockIdx.x; int b = blk >> 5; int n0 = (blk & 31) << 3;
    __shared__ float adjs[8*Nv];
    __shared__ float degs[8];
    int t = threadIdx.x;
    #pragma unroll
    for (int i = 0; i < 16; i++) {
        int idx = i*128 + t;
        int r = idx >> 8, m = idx & 255;
        adjs[idx] = adj[((size_t)b*Nv + (n0+r))*Nv + m];
    }
    __syncthreads();
    if (t < 8) adjs[t*Nv + n0 + t] += 1.0f;   // + eye self-loop
    __syncthreads();
    {
        int r = t >> 4, lane = t & 15;
        float p = 0.f;
        #pragma unroll
        for (int k = 0; k < 16; k++) p += adjs[r*Nv + lane*16 + k];
        #pragma unroll
        for (int o = 8; o > 0; o >>= 1) p += __shfl_xor_sync(0xffffffffu, p, o, 16);
        if (lane == 0) degs[r] = p;
    }
    __syncthreads();
    float acc[8];
    #pragma unroll
    for (int r = 0; r < 8; r++) acc[r] = 0.f;
    int d = t;
    for (int m = 0; m < Nv; m++) {
        float hv = hin[((size_t)b*Nv + m)*Dv + d];
        #pragma unroll
        for (int r = 0; r < 8; r++) acc[r] += adjs[r*Nv + m] * hv;
    }
    #pragma unroll
    for (int r = 0; r < 8; r++)
        g_hagg[((size_t)b*Nv + n0 + r)*Dv + d] = acc[r] / degs[r];
}

// ---------------- K3: S0 = Q_h K_h^T (64x64 tiles, grid 512) ----------------
__global__ __launch_bounds__(256) void k_s0() {
    int bh = blockIdx.x; int b = bh >> 2, h = bh & 3;
    int n0 = blockIdx.y << 6, m0 = blockIdx.z << 6;
    __shared__ float Qt[64*33];
    __shared__ float Kt[64*33];
    int t = threadIdx.x;
    #pragma unroll
    for (int i = 0; i < 2; i++) {
        int f = i*256 + t;
        int r = f >> 3, c4 = (f & 7) << 2;
        float4 v = *(const float4*)(g_q  + ((size_t)(b*Nv + n0 + r))*Dv + h*HDv + c4);
        float* p = &Qt[r*33 + c4];
        p[0]=v.x; p[1]=v.y; p[2]=v.z; p[3]=v.w;
        float4 w = *(const float4*)(g_kh + ((size_t)(b*Nv + m0 + r))*Dv + h*HDv + c4);
        float* q = &Kt[r*33 + c4];
        q[0]=w.x; q[1]=w.y; q[2]=w.z; q[3]=w.w;
    }
    __syncthreads();
    int tx = t & 15, ty = t >> 4;
    float acc[4][4];
    #pragma unroll
    for (int i = 0; i < 4; i++)
        #pragma unroll
        for (int j = 0; j < 4; j++) acc[i][j] = 0.f;
    #pragma unroll 4
    for (int e = 0; e < HDv; e++) {
        float qr[4], kr[4];
        #pragma unroll
        for (int i = 0; i < 4; i++) { qr[i] = Qt[(ty*4+i)*33 + e]; kr[i] = Kt[(tx*4+i)*33 + e]; }
        #pragma unroll
        for (int i = 0; i < 4; i++)
            #pragma unroll
            for (int j = 0; j < 4; j++) acc[i][j] += qr[i]*kr[j];
    }
    float* dst = g_S0 + (size_t)(b*Hv + h)*Nv*Nv;
    #pragma unroll
    for (int i = 0; i < 4; i++) {
        float* p = dst + (size_t)(n0 + ty*4 + i)*Nv + m0 + tx*4;
        *(float4*)p = make_float4(acc[i][0],acc[i][1],acc[i][2],acc[i][3]);
    }
}

// ---------------- K4: fused edge-scores + softmax + ae + o2 ----------------
__global__ __launch_bounds__(256) void k_att(const float* __restrict__ ef,
                                             const float* __restrict__ adj,
                                             const float* __restrict__ srcm) {
    int bn = blockIdx.x; int b = bn >> 8, n = bn & 255;
    __shared__ float efs[Nv*33];
    __shared__ float qks[Dv];
    __shared__ float ats[Hv*Nv];
    __shared__ float red[Hv*Nv];
    __shared__ float wred[32];
    __shared__ float mxs[Hv], sms[Hv];
    int t = threadIdx.x, lane = t & 31, wid = t >> 5;
    int m = t;

    float4 v[8];
    const float4* src = (const float4*)(ef + (size_t)bn*Nv*Ev);
    #pragma unroll
    for (int i = 0; i < 8; i++) v[i] = src[i*256 + t];
    float s0[Hv];
    #pragma unroll
    for (int h = 0; h < Hv; h++)
        s0[h] = g_S0[((size_t)(b*Hv + h)*Nv + n)*Nv + m];
    float w = adj[(size_t)bn*Nv + m] * srcm[(size_t)bn*Nv + m];
    if (t < Dv) qks[t] = g_qke[(size_t)bn*Dv + t];
    #pragma unroll
    for (int i = 0; i < 8; i++) {
        int fidx = (i*256 + t) << 2; int mm = fidx >> 5; int e = fidx & 31;
        float* p = &efs[mm*33 + e];
        p[0]=v[i].x; p[1]=v[i].y; p[2]=v[i].z; p[3]=v[i].w;
    }
    __syncthreads();

    float sc[Hv];
    {
        float es[Hv] = {0.f,0.f,0.f,0.f};
        #pragma unroll 8
        for (int e = 0; e < Ev; e++) {
            float fv = efs[m*33 + e];
            #pragma unroll
            for (int h = 0; h < Hv; h++) es[h] += fv * qks[h*Ev + e];
        }
        bool msk = (w == 0.0f);
        #pragma unroll
        for (int h = 0; h < Hv; h++)
            sc[h] = msk ? -1e30f : (s0[h] + es[h]) * 0.17677669529663687f;
    }

    {
        float wm[Hv];
        #pragma unroll
        for (int h = 0; h < Hv; h++) {
            wm[h] = sc[h];
            #pragma unroll
            for (int o = 16; o > 0; o >>= 1)
                wm[h] = fmaxf(wm[h], __shfl_xor_sync(0xffffffffu, wm[h], o));
        }
        if (lane == 0) {
            #pragma unroll
            for (int h = 0; h < Hv; h++) wred[h*8 + wid] = wm[h];
        }
    }
    __syncthreads();
    if (t < 32) {
        float val = wred[t];
        val = fmaxf(val, __shfl_xor_sync(0xffffffffu, val, 1));
        val = fmaxf(val, __shfl_xor_sync(0xffffffffu, val, 2));
        val = fmaxf(val, __shfl_xor_sync(0xffffffffu, val, 4));
        if ((t & 7) == 0) mxs[t >> 3] = val;
    }
    __syncthreads();

    float ex[Hv];
    {
        float ws[Hv];
        #pragma unroll
        for (int h = 0; h < Hv; h++) {
            ex[h] = __expf(sc[h] - mxs[h]);
            ws[h] = ex[h];
            #pragma unroll
            for (int o = 16; o > 0; o >>= 1)
                ws[h] += __shfl_xor_sync(0xffffffffu, ws[h], o);
        }
        if (lane == 0) {
            #pragma unroll
            for (int h = 0; h < Hv; h++) wred[h*8 + wid] = ws[h];
        }
    }
    __syncthreads();
    if (t < 32) {
        float val = wred[t];
        val += __shfl_xor_sync(0xffffffffu, val, 1);
        val += __shfl_xor_sync(0xffffffffu, val, 2);
        val += __shfl_xor_sync(0xffffffffu, val, 4);
        if ((t & 7) == 0) sms[t >> 3] = val;
    }
    __syncthreads();

    #pragma unroll
    for (int h = 0; h < Hv; h++) {
        float a = ex[h] / sms[h];
        ats[h*Nv + t] = a;
        g_at[((size_t)(b*Hv + h)*Nv + n)*Nv + m] = a;
    }
    __syncthreads();

    {
        int e = t & 31, grp = t >> 5;
        float a0=0.f,a1=0.f,a2=0.f,a3=0.f;
        int mb = grp * 32;
        #pragma unroll 4
        for (int k = 0; k < 32; k++) {
            float fv = efs[(mb+k)*33 + e];
            a0 += ats[0*Nv + mb + k] * fv;
            a1 += ats[1*Nv + mb + k] * fv;
            a2 += ats[2*Nv + mb + k] * fv;
            a3 += ats[3*Nv + mb + k] * fv;
        }
        red[grp*128 + 0*32 + e] = a0;
        red[grp*128 + 1*32 + e] = a1;
        red[grp*128 + 2*32 + e] = a2;
        red[grp*128 + 3*32 + e] = a3;
    }
    __syncthreads();
    if (t < Dv) {
        float ae = 0.f;
        #pragma unroll
        for (int g = 0; g < 8; g++) ae += red[g*128 + t];
        qks[t] = ae;
    }
    __syncthreads();
    if (t < Dv) {
        int d = t, hh = d >> 5;
        float o2 = 0.f;
        #pragma unroll
        for (int e2 = 0; e2 < Ev; e2++) o2 += g_wve[d*Ev + e2] * qks[hh*Ev + e2];
        g_o2[(size_t)bn*Dv + d] = o2;
    }
}

// ---------------- K5: o1 = attn @ v_h (32-row tiles, grid 256) ----------------
__global__ __launch_bounds__(256) void k_o1() {
    int bh = blockIdx.x; int b = bh >> 2, h = bh & 3;
    int n0 = blockIdx.y << 5;
    __shared__ float At[32*33];
    __shared__ float Vt[32*33];
    int t = threadIdx.x, tx = t & 31, ty = t >> 5;
    float acc[4];
    #pragma unroll
    for (int i = 0; i < 4; i++) acc[i] = 0.f;
    const float* attn_base = g_at + ((size_t)(b*Hv + h)*Nv + n0)*Nv;
    for (int mc = 0; mc < Nv; mc += 32) {
        {
            int row = t >> 3, c4 = (t & 7) << 2;
            float4 va = *(const float4*)(attn_base + (size_t)row*Nv + mc + c4);
            float* p = &At[row*33 + c4];
            p[0]=va.x; p[1]=va.y; p[2]=va.z; p[3]=va.w;
            float4 vv = *(const float4*)(g_vh + (size_t)(b*Nv + mc + row)*Dv + h*HDv + c4);
            float* q = &Vt[row*33 + c4];
            q[0]=vv.x; q[1]=vv.y; q[2]=vv.z; q[3]=vv.w;
        }
        __syncthreads();
        #pragma unroll 8
        for (int mm = 0; mm < 32; mm++) {
            float vv = Vt[mm*33 + tx];
            #pragma unroll
            for (int i = 0; i < 4; i++) acc[i] += At[(ty*4+i)*33 + mm] * vv;
        }
        __syncthreads();
    }
    #pragma unroll
    for (int i = 0; i < 4; i++)
        g_o1[(size_t)(b*Nv + n0 + ty*4 + i)*Dv + h*HDv + tx] = acc[i];
}

// ---------------- K6: 16 rows/CTA: out-proj + gcn-proj (parallel groups) + LN ------
__global__ __launch_bounds__(256) void k_final(const float* __restrict__ hin,
                                               const float* __restrict__ out_w,
                                               const float* __restrict__ out_b,
                                               const float* __restrict__ gcn_w,
                                               const float* __restrict__ gcn_b,
                                               const float* __restrict__ ln_g,
                                               const float* __restrict__ ln_b,
                                               float* __restrict__ out) {
    int bn0 = blockIdx.x << 4;
    int t = threadIdx.x;
    __shared__ float hs[16*Dv];
    __shared__ float os[16*Dv];
    __shared__ float hag[16*Dv];
    __shared__ float yb[16*Dv];
    __shared__ float gb[16*Dv];
    for (int i = t; i < 16*Dv; i += 256) {
        size_t gi = (size_t)bn0*Dv + i;
        os[i]  = g_o1[gi] + g_o2[gi];
        hag[i] = g_hagg[gi];
        hs[i]  = hin[gi];
    }
    __syncthreads();
    int grp = t >> 7, d = t & 127;
    {
        const float4* W4 = (const float4*)(grp ? gcn_w : out_w);
        float bias = grp ? gcn_b[d] : out_b[d];
        const float4* X4 = (const float4*)(grp ? hag : os);
        float* Y = grp ? gb : yb;
        float acc[16];
        #pragma unroll
        for (int r = 0; r < 16; r++) acc[r] = bias;
        #pragma unroll 4
        for (int j4 = 0; j4 < 32; j4++) {
            float4 w = W4[d*32 + j4];
            #pragma unroll
            for (int r = 0; r < 16; r++) {
                float4 hv = X4[r*32 + j4];
                acc[r] += w.x*hv.x + w.y*hv.y + w.z*hv.z + w.w*hv.w;
            }
        }
        #pragma unroll
        for (int r = 0; r < 16; r++) Y[r*Dv + d] = acc[r];
    }
    __syncthreads();
    // LN + final: warp w handles rows 2w, 2w+1
    int wid = t >> 5, lane = t & 31;
    const float4* hs4 = (const float4*)hs;
    const float4* yb4 = (const float4*)yb;
    const float4* gb4 = (const float4*)gb;
    const float4* lg4 = (const float4*)ln_g;
    const float4* lb4 = (const float4*)ln_b;
    #pragma unroll
    for (int rr = 0; rr < 2; rr++) {
        int r = wid*2 + rr;
        float4 a = hs4[r*32 + lane];
        float4 bq = yb4[r*32 + lane];
        float x0 = a.x + bq.x, x1 = a.y + bq.y, x2 = a.z + bq.z, x3 = a.w + bq.w;
        float s = x0 + x1 + x2 + x3;
        #pragma unroll
        for (int o = 16; o > 0; o >>= 1) s += __shfl_xor_sync(0xffffffffu, s, o);
        float mu = s * (1.0f/128.0f);
        float c0 = x0-mu, c1 = x1-mu, c2 = x2-mu, c3 = x3-mu;
        float vv = c0*c0 + c1*c1 + c2*c2 + c3*c3;
        #pragma unroll
        for (int o = 16; o > 0; o >>= 1) vv += __shfl_xor_sync(0xffffffffu, vv, o);
        float rs = rsqrtf(vv * (1.0f/128.0f) + 1e-5f);
        float4 g = lg4[lane], lb = lb4[lane], gg = gb4[r*32 + lane];
        float4 res;
        res.x = gg.x + g.x*c0*rs + lb.x;
        res.y = gg.y + g.y*c1*rs + lb.y;
        res.z = gg.z + g.z*c2*rs + lb.z;
        res.w = gg.w + g.w*c3*rs + lb.w;
        *(float4*)(out + (size_t)(bn0 + r)*Dv + lane*4) = res;
    }
}

extern "C" void kernel_launch(void* const* d_in, const int* in_sizes, int n_in,
                              void* d_out, int out_size) {
    const float* h     = (const float*)d_in[0];
    const float* adj   = (const float*)d_in[1];
    const float* ef    = (const float*)d_in[2];
    const float* smk   = (const float*)d_in[3];
    const float* gcn_w = (const float*)d_in[4];
    const float* gcn_b = (const float*)d_in[5];
    const float* edge_w= (const float*)d_in[6];
    const float* edge_b= (const float*)d_in[7];
    const float* wq    = (const float*)d_in[8];
    const float* wk    = (const float*)d_in[9];
    const float* wv    = (const float*)d_in[10];
    const float* bq    = (const float*)d_in[11];
    const float* bk    = (const float*)d_in[12];
    const float* bv    = (const float*)d_in[13];
    const float* out_w = (const float*)d_in[14];
    const float* out_b = (const float*)d_in[15];
    const float* ln_g  = (const float*)d_in[16];
    const float* ln_b  = (const float*)d_in[17];
    float* out = (float*)d_out;

    k_prep <<<33, 128>>>(wk, wv, edge_w, edge_b, bk, bv);
    k_proj <<<BN/16, 384>>>(h, wq, wk, wv, bq);
    k_gcn  <<<Bv*32, 128>>>(h, adj);
    k_s0   <<<dim3(Bv*Hv, 4, 4), 256>>>();
    k_att  <<<BN, 256>>>(ef, adj, smk);
    k_o1   <<<dim3(Bv*Hv, 8), 256>>>();
    k_final<<<BN/16, 256>>>(h, out_w, out_b, gcn_w, gcn_b, ln_g, ln_b, out);
}

// round 5
// speedup vs baseline: 4.0764x; 1.0568x over previous
#include <cuda_runtime.h>

#define Bv 8
#define Nv 256
#define Dv 128
#define Ev 32
#define Hv 4
#define HDv 32
#define BN (Bv*Nv)

// ---------------- scratch (device globals; no allocation allowed) ----------------
__device__ float g_wke[Dv*Ev];
__device__ float g_wve[Dv*Ev];
__device__ float g_q  [BN*Dv];
__device__ float g_kh [BN*Dv];
__device__ float g_vh [BN*Dv];
__device__ float g_S0 [Bv*Hv*Nv*Nv];    // [b][h][n][m]
__device__ float g_at [Bv*Hv*Nv*Nv];    // attention probs
__device__ float g_o1 [BN*Dv];
__device__ float g_o2 [BN*Dv];
__device__ float g_hagg[BN*Dv];

// ---------------- K0: fused front: proj (blk<256) | gcn (256..511) | prep (512..543) ----
__global__ __launch_bounds__(384) void k_front(const float* __restrict__ hin,
                                               const float* __restrict__ adj,
                                               const float* __restrict__ wq,
                                               const float* __restrict__ wk,
                                               const float* __restrict__ wv,
                                               const float* __restrict__ bq,
                                               const float* __restrict__ bk,
                                               const float* __restrict__ bv,
                                               const float* __restrict__ edge_w,
                                               const float* __restrict__ edge_b) {
    int blk = blockIdx.x, t = threadIdx.x;
    if (blk < 256) {
        // ---- projections, 8 rows/CTA; edge_b as virtual 9th row for bias fold ----
        __shared__ float hs[9*Dv];
        int bn0 = blk << 3;
        for (int i = t; i < 9*Dv; i += 384)
            hs[i] = (i < 8*Dv) ? hin[(size_t)bn0*Dv + i] : edge_b[i - 8*Dv];
        __syncthreads();
        int mat = t >> 7, d = t & 127;
        const float* W = (mat == 0) ? wq : (mat == 1) ? wk : wv;
        float bias = (mat == 0) ? bq[d] : (mat == 1) ? bk[d] : bv[d];
        float acc[9];
        #pragma unroll
        for (int r = 0; r < 9; r++) acc[r] = 0.f;
        const float4* W4 = (const float4*)W;
        const float4* hs4 = (const float4*)hs;
        #pragma unroll 4
        for (int j4 = 0; j4 < 32; j4++) {
            float4 w = W4[d*32 + j4];
            #pragma unroll
            for (int r = 0; r < 9; r++) {
                float4 hv = hs4[r*32 + j4];
                acc[r] += w.x*hv.x + w.y*hv.y + w.z*hv.z + w.w*hv.w;
            }
        }
        float* dst = (mat == 0) ? g_q : (mat == 1) ? g_kh : g_vh;
        float cadd = (mat == 0) ? bias : (bias + acc[8]);   // k/v get wk@edge_b fold
        #pragma unroll
        for (int r = 0; r < 8; r++)
            dst[(size_t)(bn0 + r)*Dv + d] = acc[r] + cadd;
    } else if (blk < 512) {
        // ---- GCN aggregation, 8 rows/CTA, 3 m-groups ----
        __shared__ float adjs[8*Nv];
        __shared__ float part[3*8*Dv];
        __shared__ float degs[8];
        int g = blk - 256; int b = g >> 5; int n0 = (g & 31) << 3;
        for (int i = t; i < 8*Nv; i += 384) {
            int r = i >> 8, m = i & 255;
            adjs[i] = adj[((size_t)b*Nv + (n0+r))*Nv + m];
        }
        __syncthreads();
        if (t < 8) adjs[t*Nv + n0 + t] += 1.0f;
        __syncthreads();
        if (t < 128) {
            int r = t >> 4, lane = t & 15;
            float p = 0.f;
            #pragma unroll
            for (int k = 0; k < 16; k++) p += adjs[r*Nv + lane*16 + k];
            #pragma unroll
            for (int o = 8; o > 0; o >>= 1) p += __shfl_xor_sync(0xffffffffu, p, o, 16);
            if (lane == 0) degs[r] = p;
        }
        __syncthreads();
        int grp = t >> 7, d = t & 127;
        const int mlo = (grp == 0) ? 0 : (grp == 1) ? 86 : 171;
        const int mhi = (grp == 0) ? 86 : (grp == 1) ? 171 : 256;
        float acc[8];
        #pragma unroll
        for (int r = 0; r < 8; r++) acc[r] = 0.f;
        for (int m = mlo; m < mhi; m++) {
            float hv = hin[((size_t)b*Nv + m)*Dv + d];
            #pragma unroll
            for (int r = 0; r < 8; r++) acc[r] += adjs[r*Nv + m] * hv;
        }
        #pragma unroll
        for (int r = 0; r < 8; r++) part[grp*8*Dv + r*Dv + d] = acc[r];
        __syncthreads();
        if (t < 128) {
            #pragma unroll
            for (int r = 0; r < 8; r++) {
                float s = part[0*8*Dv + r*Dv + t] + part[1*8*Dv + r*Dv + t] + part[2*8*Dv + r*Dv + t];
                g_hagg[((size_t)b*Nv + n0 + r)*Dv + t] = s / degs[r];
            }
        }
    } else {
        // ---- prep: wke/wve = wk@edge_w, wv@edge_w ----
        if (t < 128) {
            int pb = blk - 512;          // 0..31
            int dl = t >> 5, e = t & 31;
            int d = pb * 4 + dl;
            float sk = 0.f, sv = 0.f;
            #pragma unroll 8
            for (int j = 0; j < Dv; j++) {
                float ew = edge_w[j*Ev + e];
                sk += wk[d*Dv + j] * ew;
                sv += wv[d*Dv + j] * ew;
            }
            g_wke[d*Ev + e] = sk;
            g_wve[d*Ev + e] = sv;
        }
    }
}

// ---------------- K1: S0 = Q_h K_h^T (32x64 tiles, grid 1024) ----------------
__global__ __launch_bounds__(256) void k_s0() {
    int bh = blockIdx.x; int b = bh >> 2, h = bh & 3;
    int n0 = blockIdx.y << 5, m0 = blockIdx.z << 6;
    __shared__ float Qt[32*33];
    __shared__ float Kt[64*33];
    int t = threadIdx.x;
    if (t < 256) {
        int r = t >> 3, c4 = (t & 7) << 2;
        if (t < 256) { // Kt: 2 rows-chunks
            float4 w0 = *(const float4*)(g_kh + ((size_t)(b*Nv + m0 + r))*Dv + h*HDv + c4);
            float* q0 = &Kt[r*33 + c4];
            q0[0]=w0.x; q0[1]=w0.y; q0[2]=w0.z; q0[3]=w0.w;
            float4 w1 = *(const float4*)(g_kh + ((size_t)(b*Nv + m0 + 32 + r))*Dv + h*HDv + c4);
            float* q1 = &Kt[(32+r)*33 + c4];
            q1[0]=w1.x; q1[1]=w1.y; q1[2]=w1.z; q1[3]=w1.w;
        }
        if (t < 256 && r < 32) {
            float4 v = *(const float4*)(g_q + ((size_t)(b*Nv + n0 + r))*Dv + h*HDv + c4);
            float* p = &Qt[r*33 + c4];
            p[0]=v.x; p[1]=v.y; p[2]=v.z; p[3]=v.w;
        }
    }
    __syncthreads();
    int tx = t & 15, ty = t >> 4;       // tx: 4 m-cols, ty: 2 n-rows
    float acc[2][4];
    #pragma unroll
    for (int i = 0; i < 2; i++)
        #pragma unroll
        for (int j = 0; j < 4; j++) acc[i][j] = 0.f;
    #pragma unroll 4
    for (int e = 0; e < HDv; e++) {
        float qr[2], kr[4];
        qr[0] = Qt[(ty*2+0)*33 + e];
        qr[1] = Qt[(ty*2+1)*33 + e];
        #pragma unroll
        for (int j = 0; j < 4; j++) kr[j] = Kt[(tx*4+j)*33 + e];
        #pragma unroll
        for (int i = 0; i < 2; i++)
            #pragma unroll
            for (int j = 0; j < 4; j++) acc[i][j] += qr[i]*kr[j];
    }
    float* dst = g_S0 + (size_t)(b*Hv + h)*Nv*Nv;
    #pragma unroll
    for (int i = 0; i < 2; i++) {
        float* p = dst + (size_t)(n0 + ty*2 + i)*Nv + m0 + tx*4;
        *(float4*)p = make_float4(acc[i][0],acc[i][1],acc[i][2],acc[i][3]);
    }
}

// ---------------- K2: fused edge-scores + softmax + ae + o2 (+inline qk_e) ---------
__global__ __launch_bounds__(256) void k_att(const float* __restrict__ ef,
                                             const float* __restrict__ adj,
                                             const float* __restrict__ srcm) {
    int bn = blockIdx.x; int b = bn >> 8, n = bn & 255;
    __shared__ float efs[Nv*33];
    __shared__ float qrow[Dv];
    __shared__ float qks[Dv];
    __shared__ float ats[Hv*Nv];
    __shared__ float red[Hv*Nv];
    __shared__ float wred[32];
    __shared__ float mxs[Hv], sms[Hv];
    int t = threadIdx.x, lane = t & 31, wid = t >> 5;
    int m = t;

    float4 v[8];
    const float4* src = (const float4*)(ef + (size_t)bn*Nv*Ev);
    #pragma unroll
    for (int i = 0; i < 8; i++) v[i] = src[i*256 + t];
    float s0[Hv];
    #pragma unroll
    for (int h = 0; h < Hv; h++)
        s0[h] = g_S0[((size_t)(b*Hv + h)*Nv + n)*Nv + m];
    float w = adj[(size_t)bn*Nv + m] * srcm[(size_t)bn*Nv + m];
    if (t < Dv) qrow[t] = g_q[(size_t)bn*Dv + t];
    __syncthreads();
    // qk_e inline: qks[h*32+e] = sum_j q[h*32+j] * wke[(h*32+j)*32+e]
    if (t < Dv) {
        int hh = (t >> 5) << 5, e = t & 31;
        float s = 0.f;
        #pragma unroll 8
        for (int j = 0; j < 32; j++) s += qrow[hh + j] * g_wke[(hh + j)*Ev + e];
        qks[t] = s;
    }
    #pragma unroll
    for (int i = 0; i < 8; i++) {
        int fidx = (i*256 + t) << 2; int mm = fidx >> 5; int e = fidx & 31;
        float* p = &efs[mm*33 + e];
        p[0]=v[i].x; p[1]=v[i].y; p[2]=v[i].z; p[3]=v[i].w;
    }
    __syncthreads();

    float sc[Hv];
    {
        float es[Hv] = {0.f,0.f,0.f,0.f};
        #pragma unroll 8
        for (int e = 0; e < Ev; e++) {
            float fv = efs[m*33 + e];
            #pragma unroll
            for (int h = 0; h < Hv; h++) es[h] += fv * qks[h*Ev + e];
        }
        bool msk = (w == 0.0f);
        #pragma unroll
        for (int h = 0; h < Hv; h++)
            sc[h] = msk ? -1e30f : (s0[h] + es[h]) * 0.17677669529663687f;
    }

    {
        float wm[Hv];
        #pragma unroll
        for (int h = 0; h < Hv; h++) {
            wm[h] = sc[h];
            #pragma unroll
            for (int o = 16; o > 0; o >>= 1)
                wm[h] = fmaxf(wm[h], __shfl_xor_sync(0xffffffffu, wm[h], o));
        }
        if (lane == 0) {
            #pragma unroll
            for (int h = 0; h < Hv; h++) wred[h*8 + wid] = wm[h];
        }
    }
    __syncthreads();
    if (t < 32) {
        float val = wred[t];
        val = fmaxf(val, __shfl_xor_sync(0xffffffffu, val, 1));
        val = fmaxf(val, __shfl_xor_sync(0xffffffffu, val, 2));
        val = fmaxf(val, __shfl_xor_sync(0xffffffffu, val, 4));
        if ((t & 7) == 0) mxs[t >> 3] = val;
    }
    __syncthreads();

    float ex[Hv];
    {
        float ws[Hv];
        #pragma unroll
        for (int h = 0; h < Hv; h++) {
            ex[h] = __expf(sc[h] - mxs[h]);
            ws[h] = ex[h];
            #pragma unroll
            for (int o = 16; o > 0; o >>= 1)
                ws[h] += __shfl_xor_sync(0xffffffffu, ws[h], o);
        }
        if (lane == 0) {
            #pragma unroll
            for (int h = 0; h < Hv; h++) wred[h*8 + wid] = ws[h];
        }
    }
    __syncthreads();
    if (t < 32) {
        float val = wred[t];
        val += __shfl_xor_sync(0xffffffffu, val, 1);
        val += __shfl_xor_sync(0xffffffffu, val, 2);
        val += __shfl_xor_sync(0xffffffffu, val, 4);
        if ((t & 7) == 0) sms[t >> 3] = val;
    }
    __syncthreads();

    #pragma unroll
    for (int h = 0; h < Hv; h++) {
        float a = ex[h] / sms[h];
        ats[h*Nv + t] = a;
        g_at[((size_t)(b*Hv + h)*Nv + n)*Nv + m] = a;
    }
    __syncthreads();

    {
        int e = t & 31, grp = t >> 5;
        float a0=0.f,a1=0.f,a2=0.f,a3=0.f;
        int mb = grp * 32;
        #pragma unroll 4
        for (int k = 0; k < 32; k++) {
            float fv = efs[(mb+k)*33 + e];
            a0 += ats[0*Nv + mb + k] * fv;
            a1 += ats[1*Nv + mb + k] * fv;
            a2 += ats[2*Nv + mb + k] * fv;
            a3 += ats[3*Nv + mb + k] * fv;
        }
        red[grp*128 + 0*32 + e] = a0;
        red[grp*128 + 1*32 + e] = a1;
        red[grp*128 + 2*32 + e] = a2;
        red[grp*128 + 3*32 + e] = a3;
    }
    __syncthreads();
    if (t < Dv) {
        float ae = 0.f;
        #pragma unroll
        for (int g = 0; g < 8; g++) ae += red[g*128 + t];
        qks[t] = ae;
    }
    __syncthreads();
    if (t < Dv) {
        int d = t, hh = d >> 5;
        float o2 = 0.f;
        #pragma unroll
        for (int e2 = 0; e2 < Ev; e2++) o2 += g_wve[d*Ev + e2] * qks[hh*Ev + e2];
        g_o2[(size_t)bn*Dv + d] = o2;
    }
}

// ---------------- K3: o1 = attn @ v_h (16-row tiles, grid 512) ----------------
__global__ __launch_bounds__(256) void k_o1() {
    int bh = blockIdx.x; int b = bh >> 2, h = bh & 3;
    int n0 = blockIdx.y << 4;
    __shared__ float At[16*33];
    __shared__ float Vt[32*33];
    int t = threadIdx.x, tx = t & 31, ty = t >> 5;
    float acc[2];
    acc[0] = 0.f; acc[1] = 0.f;
    const float* attn_base = g_at + ((size_t)(b*Hv + h)*Nv + n0)*Nv;
    for (int mc = 0; mc < Nv; mc += 32) {
        if (t < 128) {
            int row = t >> 3, c4 = (t & 7) << 2;
            float4 va = *(const float4*)(attn_base + (size_t)row*Nv + mc + c4);
            float* p = &At[row*33 + c4];
            p[0]=va.x; p[1]=va.y; p[2]=va.z; p[3]=va.w;
        }
        {
            int row = t >> 3, c4 = (t & 7) << 2;
            float4 vv = *(const float4*)(g_vh + (size_t)(b*Nv + mc + row)*Dv + h*HDv + c4);
            float* q = &Vt[row*33 + c4];
            q[0]=vv.x; q[1]=vv.y; q[2]=vv.z; q[3]=vv.w;
        }
        __syncthreads();
        #pragma unroll 8
        for (int mm = 0; mm < 32; mm++) {
            float vv = Vt[mm*33 + tx];
            acc[0] += At[(ty*2+0)*33 + mm] * vv;
            acc[1] += At[(ty*2+1)*33 + mm] * vv;
        }
        __syncthreads();
    }
    g_o1[(size_t)(b*Nv + n0 + ty*2 + 0)*Dv + h*HDv + tx] = acc[0];
    g_o1[(size_t)(b*Nv + n0 + ty*2 + 1)*Dv + h*HDv + tx] = acc[1];
}

// ---------------- K4: 8 rows/CTA: out-proj + gcn-proj + LN ----------------
__global__ __launch_bounds__(256) void k_final(const float* __restrict__ hin,
                                               const float* __restrict__ out_w,
                                               const float* __restrict__ out_b,
                                               const float* __restrict__ gcn_w,
                                               const float* __restrict__ gcn_b,
                                               const float* __restrict__ ln_g,
                                               const float* __restrict__ ln_b,
                                               float* __restrict__ out) {
    int bn0 = blockIdx.x << 3;
    int t = threadIdx.x;
    __shared__ float hs[8*Dv];
    __shared__ float os[8*Dv];
    __shared__ float hag[8*Dv];
    __shared__ float yb[8*Dv];
    __shared__ float gb[8*Dv];
    for (int i = t; i < 8*Dv; i += 256) {
        size_t gi = (size_t)bn0*Dv + i;
        os[i]  = g_o1[gi] + g_o2[gi];
        hag[i] = g_hagg[gi];
        hs[i]  = hin[gi];
    }
    __syncthreads();
    int grp = t >> 7, d = t & 127;
    {
        const float4* W4 = (const float4*)(grp ? gcn_w : out_w);
        float bias = grp ? gcn_b[d] : out_b[d];
        const float4* X4 = (const float4*)(grp ? hag : os);
        float* Y = grp ? gb : yb;
        float acc[8];
        #pragma unroll
        for (int r = 0; r < 8; r++) acc[r] = bias;
        #pragma unroll 4
        for (int j4 = 0; j4 < 32; j4++) {
            float4 w = W4[d*32 + j4];
            #pragma unroll
            for (int r = 0; r < 8; r++) {
                float4 hv = X4[r*32 + j4];
                acc[r] += w.x*hv.x + w.y*hv.y + w.z*hv.z + w.w*hv.w;
            }
        }
        #pragma unroll
        for (int r = 0; r < 8; r++) Y[r*Dv + d] = acc[r];
    }
    __syncthreads();
    int wid = t >> 5, lane = t & 31;
    const float4* hs4 = (const float4*)hs;
    const float4* yb4 = (const float4*)yb;
    const float4* gb4 = (const float4*)gb;
    const float4* lg4 = (const float4*)ln_g;
    const float4* lb4 = (const float4*)ln_b;
    {
        int r = wid;
        float4 a = hs4[r*32 + lane];
        float4 bq = yb4[r*32 + lane];
        float x0 = a.x + bq.x, x1 = a.y + bq.y, x2 = a.z + bq.z, x3 = a.w + bq.w;
        float s = x0 + x1 + x2 + x3;
        #pragma unroll
        for (int o = 16; o > 0; o >>= 1) s += __shfl_xor_sync(0xffffffffu, s, o);
        float mu = s * (1.0f/128.0f);
        float c0 = x0-mu, c1 = x1-mu, c2 = x2-mu, c3 = x3-mu;
        float vv = c0*c0 + c1*c1 + c2*c2 + c3*c3;
        #pragma unroll
        for (int o = 16; o > 0; o >>= 1) vv += __shfl_xor_sync(0xffffffffu, vv, o);
        float rs = rsqrtf(vv * (1.0f/128.0f) + 1e-5f);
        float4 g = lg4[lane], lb = lb4[lane], gg = gb4[r*32 + lane];
        float4 res;
        res.x = gg.x + g.x*c0*rs + lb.x;
        res.y = gg.y + g.y*c1*rs + lb.y;
        res.z = gg.z + g.z*c2*rs + lb.z;
        res.w = gg.w + g.w*c3*rs + lb.w;
        *(float4*)(out + (size_t)(bn0 + r)*Dv + lane*4) = res;
    }
}

extern "C" void kernel_launch(void* const* d_in, const int* in_sizes, int n_in,
                              void* d_out, int out_size) {
    const float* h     = (const float*)d_in[0];
    const float* adj   = (const float*)d_in[1];
    const float* ef    = (const float*)d_in[2];
    const float* smk   = (const float*)d_in[3];
    const float* gcn_w = (const float*)d_in[4];
    const float* gcn_b = (const float*)d_in[5];
    const float* edge_w= (const float*)d_in[6];
    const float* edge_b= (const float*)d_in[7];
    const float* wq    = (const float*)d_in[8];
    const float* wk    = (const float*)d_in[9];
    const float* wv    = (const float*)d_in[10];
    const float* bq    = (const float*)d_in[11];
    const float* bk    = (const float*)d_in[12];
    const float* bv    = (const float*)d_in[13];
    const float* out_w = (const float*)d_in[14];
    const float* out_b = (const float*)d_in[15];
    const float* ln_g  = (const float*)d_in[16];
    const float* ln_b  = (const float*)d_in[17];
    float* out = (float*)d_out;

    k_front<<<544, 384>>>(h, adj, wq, wk, wv, bq, bk, bv, edge_w, edge_b);
    k_s0   <<<dim3(Bv*Hv, 8, 4), 256>>>();
    k_att  <<<BN, 256>>>(ef, adj, smk);
    k_o1   <<<dim3(Bv*Hv, 16), 256>>>();
    k_final<<<BN/8, 256>>>(h, out_w, out_b, gcn_w, gcn_b, ln_g, ln_b, out);
}

// round 6
// speedup vs baseline: 4.1243x; 1.0118x over previous
#include <cuda_runtime.h>

#define Bv 8
#define Nv 256
#define Dv 128
#define Ev 32
#define Hv 4
#define HDv 32
#define BN (Bv*Nv)

// ---------------- scratch (device globals; no allocation allowed) ----------------
__device__ float g_wke[Dv*Ev];
__device__ float g_wve[Dv*Ev];
__device__ float g_q  [BN*Dv];
__device__ float g_kh [BN*Dv];
__device__ float g_vh [BN*Dv];
__device__ float g_S0 [Bv*Hv*Nv*Nv];    // [b][h][n][m]
__device__ float g_at [Bv*Hv*Nv*Nv];    // attention probs
__device__ float g_o1 [BN*Dv];
__device__ float g_o2 [BN*Dv];
__device__ float g_hagg[BN*Dv];

// ---------------- K0: fused front: proj (blk<256) | gcn (256..511) | prep (512..543) ----
__global__ __launch_bounds__(384) void k_front(const float* __restrict__ hin,
                                               const float* __restrict__ adj,
                                               const float* __restrict__ wq,
                                               const float* __restrict__ wk,
                                               const float* __restrict__ wv,
                                               const float* __restrict__ bq,
                                               const float* __restrict__ bk,
                                               const float* __restrict__ bv,
                                               const float* __restrict__ edge_w,
                                               const float* __restrict__ edge_b) {
    int blk = blockIdx.x, t = threadIdx.x;
    if (blk < 256) {
        __shared__ float hs[9*Dv];
        int bn0 = blk << 3;
        for (int i = t; i < 9*Dv; i += 384)
            hs[i] = (i < 8*Dv) ? hin[(size_t)bn0*Dv + i] : edge_b[i - 8*Dv];
        __syncthreads();
        int mat = t >> 7, d = t & 127;
        const float* W = (mat == 0) ? wq : (mat == 1) ? wk : wv;
        float bias = (mat == 0) ? bq[d] : (mat == 1) ? bk[d] : bv[d];
        float acc[9];
        #pragma unroll
        for (int r = 0; r < 9; r++) acc[r] = 0.f;
        const float4* W4 = (const float4*)W;
        const float4* hs4 = (const float4*)hs;
        #pragma unroll 4
        for (int j4 = 0; j4 < 32; j4++) {
            float4 w = W4[d*32 + j4];
            #pragma unroll
            for (int r = 0; r < 9; r++) {
                float4 hv = hs4[r*32 + j4];
                acc[r] += w.x*hv.x + w.y*hv.y + w.z*hv.z + w.w*hv.w;
            }
        }
        float* dst = (mat == 0) ? g_q : (mat == 1) ? g_kh : g_vh;
        float cadd = (mat == 0) ? bias : (bias + acc[8]);
        #pragma unroll
        for (int r = 0; r < 8; r++)
            dst[(size_t)(bn0 + r)*Dv + d] = acc[r] + cadd;
    } else if (blk < 512) {
        __shared__ float adjs[8*Nv];
        __shared__ float part[3*8*Dv];
        __shared__ float degs[8];
        int g = blk - 256; int b = g >> 5; int n0 = (g & 31) << 3;
        for (int i = t; i < 8*Nv; i += 384) {
            int r = i >> 8, m = i & 255;
            adjs[i] = adj[((size_t)b*Nv + (n0+r))*Nv + m];
        }
        __syncthreads();
        if (t < 8) adjs[t*Nv + n0 + t] += 1.0f;
        __syncthreads();
        if (t < 128) {
            int r = t >> 4, lane = t & 15;
            float p = 0.f;
            #pragma unroll
            for (int k = 0; k < 16; k++) p += adjs[r*Nv + lane*16 + k];
            #pragma unroll
            for (int o = 8; o > 0; o >>= 1) p += __shfl_xor_sync(0xffffffffu, p, o, 16);
            if (lane == 0) degs[r] = p;
        }
        __syncthreads();
        int grp = t >> 7, d = t & 127;
        const int mlo = (grp == 0) ? 0 : (grp == 1) ? 86 : 171;
        const int mhi = (grp == 0) ? 86 : (grp == 1) ? 171 : 256;
        float acc[8];
        #pragma unroll
        for (int r = 0; r < 8; r++) acc[r] = 0.f;
        for (int m = mlo; m < mhi; m++) {
            float hv = hin[((size_t)b*Nv + m)*Dv + d];
            #pragma unroll
            for (int r = 0; r < 8; r++) acc[r] += adjs[r*Nv + m] * hv;
        }
        #pragma unroll
        for (int r = 0; r < 8; r++) part[grp*8*Dv + r*Dv + d] = acc[r];
        __syncthreads();
        if (t < 128) {
            #pragma unroll
            for (int r = 0; r < 8; r++) {
                float s = part[0*8*Dv + r*Dv + t] + part[1*8*Dv + r*Dv + t] + part[2*8*Dv + r*Dv + t];
                g_hagg[((size_t)b*Nv + n0 + r)*Dv + t] = s / degs[r];
            }
        }
    } else {
        if (t < 128) {
            int pb = blk - 512;
            int dl = t >> 5, e = t & 31;
            int d = pb * 4 + dl;
            float sk = 0.f, sv = 0.f;
            #pragma unroll 8
            for (int j = 0; j < Dv; j++) {
                float ew = edge_w[j*Ev + e];
                sk += wk[d*Dv + j] * ew;
                sv += wv[d*Dv + j] * ew;
            }
            g_wke[d*Ev + e] = sk;
            g_wve[d*Ev + e] = sv;
        }
    }
}

// ---------------- K1: S0 = Q_h K_h^T (32x64 tiles, grid 1024) ----------------
__global__ __launch_bounds__(256) void k_s0() {
    int bh = blockIdx.x; int b = bh >> 2, h = bh & 3;
    int n0 = blockIdx.y << 5, m0 = blockIdx.z << 6;
    __shared__ float Qt[32*33];
    __shared__ float Kt[64*33];
    int t = threadIdx.x;
    {
        int r = t >> 3, c4 = (t & 7) << 2;
        float4 w0 = *(const float4*)(g_kh + ((size_t)(b*Nv + m0 + r))*Dv + h*HDv + c4);
        float* q0 = &Kt[r*33 + c4];
        q0[0]=w0.x; q0[1]=w0.y; q0[2]=w0.z; q0[3]=w0.w;
        float4 w1 = *(const float4*)(g_kh + ((size_t)(b*Nv + m0 + 32 + r))*Dv + h*HDv + c4);
        float* q1 = &Kt[(32+r)*33 + c4];
        q1[0]=w1.x; q1[1]=w1.y; q1[2]=w1.z; q1[3]=w1.w;
        if (r < 32) {
            float4 v = *(const float4*)(g_q + ((size_t)(b*Nv + n0 + r))*Dv + h*HDv + c4);
            float* p = &Qt[r*33 + c4];
            p[0]=v.x; p[1]=v.y; p[2]=v.z; p[3]=v.w;
        }
    }
    __syncthreads();
    int tx = t & 15, ty = t >> 4;
    float acc[2][4];
    #pragma unroll
    for (int i = 0; i < 2; i++)
        #pragma unroll
        for (int j = 0; j < 4; j++) acc[i][j] = 0.f;
    #pragma unroll 4
    for (int e = 0; e < HDv; e++) {
        float qr[2], kr[4];
        qr[0] = Qt[(ty*2+0)*33 + e];
        qr[1] = Qt[(ty*2+1)*33 + e];
        #pragma unroll
        for (int j = 0; j < 4; j++) kr[j] = Kt[(tx*4+j)*33 + e];
        #pragma unroll
        for (int i = 0; i < 2; i++)
            #pragma unroll
            for (int j = 0; j < 4; j++) acc[i][j] += qr[i]*kr[j];
    }
    float* dst = g_S0 + (size_t)(b*Hv + h)*Nv*Nv;
    #pragma unroll
    for (int i = 0; i < 2; i++) {
        float* p = dst + (size_t)(n0 + ty*2 + i)*Nv + m0 + tx*4;
        *(float4*)p = make_float4(acc[i][0],acc[i][1],acc[i][2],acc[i][3]);
    }
}

// ---------------- K2: fused edge-scores + softmax (no-max) + ae + o2 ---------------
__global__ __launch_bounds__(256) void k_att(const float* __restrict__ ef,
                                             const float* __restrict__ adj,
                                             const float* __restrict__ srcm) {
    int bn = blockIdx.x; int b = bn >> 8, n = bn & 255;
    __shared__ float efs[Nv*33];
    __shared__ float qrow[Dv];
    __shared__ float qks[Dv];
    __shared__ float ats[Hv*Nv];
    __shared__ float red[Hv*Nv];
    __shared__ float wred[32];
    __shared__ float sms[Hv];
    int t = threadIdx.x, lane = t & 31, wid = t >> 5;
    int m = t;

    float4 v[8];
    const float4* src = (const float4*)(ef + (size_t)bn*Nv*Ev);
    #pragma unroll
    for (int i = 0; i < 8; i++) v[i] = src[i*256 + t];
    float s0[Hv];
    #pragma unroll
    for (int h = 0; h < Hv; h++)
        s0[h] = g_S0[((size_t)(b*Hv + h)*Nv + n)*Nv + m];
    float w = adj[(size_t)bn*Nv + m] * srcm[(size_t)bn*Nv + m];
    if (t < Dv) qrow[t] = g_q[(size_t)bn*Dv + t];
    __syncthreads();
    if (t < Dv) {
        int hh = (t >> 5) << 5, e = t & 31;
        float s = 0.f;
        #pragma unroll 8
        for (int j = 0; j < 32; j++) s += qrow[hh + j] * g_wke[(hh + j)*Ev + e];
        qks[t] = s;
    }
    #pragma unroll
    for (int i = 0; i < 8; i++) {
        int fidx = (i*256 + t) << 2; int mm = fidx >> 5; int e = fidx & 31;
        float* p = &efs[mm*33 + e];
        p[0]=v[i].x; p[1]=v[i].y; p[2]=v[i].z; p[3]=v[i].w;
    }
    __syncthreads();

    float ex[Hv];
    {
        float es[Hv] = {0.f,0.f,0.f,0.f};
        #pragma unroll 8
        for (int e = 0; e < Ev; e++) {
            float fv = efs[m*33 + e];
            #pragma unroll
            for (int h = 0; h < Hv; h++) es[h] += fv * qks[h*Ev + e];
        }
        bool msk = (w == 0.0f);
        // scores bounded (|score| ~ <= 12): exp without max-shift is safe;
        // masked -> exp(-1e30) == 0
        #pragma unroll
        for (int h = 0; h < Hv; h++) {
            float sc = msk ? -1e30f : (s0[h] + es[h]) * 0.17677669529663687f;
            ex[h] = __expf(sc);
        }
    }

    {
        float ws[Hv];
        #pragma unroll
        for (int h = 0; h < Hv; h++) {
            ws[h] = ex[h];
            #pragma unroll
            for (int o = 16; o > 0; o >>= 1)
                ws[h] += __shfl_xor_sync(0xffffffffu, ws[h], o);
        }
        if (lane == 0) {
            #pragma unroll
            for (int h = 0; h < Hv; h++) wred[h*8 + wid] = ws[h];
        }
    }
    __syncthreads();
    if (t < 32) {
        float val = wred[t];
        val += __shfl_xor_sync(0xffffffffu, val, 1);
        val += __shfl_xor_sync(0xffffffffu, val, 2);
        val += __shfl_xor_sync(0xffffffffu, val, 4);
        if ((t & 7) == 0) sms[t >> 3] = val;
    }
    __syncthreads();

    #pragma unroll
    for (int h = 0; h < Hv; h++) {
        float a = ex[h] / sms[h];
        ats[h*Nv + t] = a;
        g_at[((size_t)(b*Hv + h)*Nv + n)*Nv + m] = a;
    }
    __syncthreads();

    {
        int e = t & 31, grp = t >> 5;
        float a0=0.f,a1=0.f,a2=0.f,a3=0.f;
        int mb = grp * 32;
        #pragma unroll 4
        for (int k = 0; k < 32; k++) {
            float fv = efs[(mb+k)*33 + e];
            a0 += ats[0*Nv + mb + k] * fv;
            a1 += ats[1*Nv + mb + k] * fv;
            a2 += ats[2*Nv + mb + k] * fv;
            a3 += ats[3*Nv + mb + k] * fv;
        }
        red[grp*128 + 0*32 + e] = a0;
        red[grp*128 + 1*32 + e] = a1;
        red[grp*128 + 2*32 + e] = a2;
        red[grp*128 + 3*32 + e] = a3;
    }
    __syncthreads();
    if (t < Dv) {
        float ae = 0.f;
        #pragma unroll
        for (int g = 0; g < 8; g++) ae += red[g*128 + t];
        qks[t] = ae;
    }
    __syncthreads();
    if (t < Dv) {
        int d = t, hh = d >> 5;
        float o2 = 0.f;
        #pragma unroll
        for (int e2 = 0; e2 < Ev; e2++) o2 += g_wve[d*Ev + e2] * qks[hh*Ev + e2];
        g_o2[(size_t)bn*Dv + d] = o2;
    }
}

// ---------------- K3: o1 = attn @ v_h -- swizzled smem, vector LDS, split-K --------
// grid (32 bh, 16 ntiles, 2 dhalf), 256 threads
__global__ __launch_bounds__(256) void k_o1() {
    int bh = blockIdx.x; int b = bh >> 2, h = bh & 3;
    int n0 = blockIdx.y << 4;      // 16 n-rows
    int dh = blockIdx.z;           // 16-d half of this head
    __shared__ float At2[16*256];  // [n][m], word-XOR swizzle: At2[r*256 + (m^r)]
    __shared__ float Vt[256*16];   // [m][d], quad swizzle: quad' = q ^ ((m>>1)&3)
    int t = threadIdx.x;
    int tz = t >> 6;               // K-quarter (64 m each)
    int ty = (t >> 2) & 15;        // n row
    int tx = t & 3;                // d quad

    // stage attn tile (16 x 256)
    const float* abase = g_at + ((size_t)bh*Nv + n0)*Nv;
    {
        int r = t & 15, kq = t >> 4;      // 16 threads per row, 16 m each
        int mb = kq << 4;
        #pragma unroll
        for (int j = 0; j < 4; j++) {
            float4 va = *(const float4*)(abase + (size_t)r*Nv + mb + (j<<2));
            At2[r*256 + ((mb+(j<<2)+0) ^ r)] = va.x;
            At2[r*256 + ((mb+(j<<2)+1) ^ r)] = va.y;
            At2[r*256 + ((mb+(j<<2)+2) ^ r)] = va.z;
            At2[r*256 + ((mb+(j<<2)+3) ^ r)] = va.w;
        }
    }
    // stage v_h tile (256 x 16), one m-row per thread
    {
        int m = t;
        const float4* vsrc = (const float4*)(g_vh + (size_t)(b*Nv + m)*Dv + h*HDv + dh*16);
        int s = (m >> 1) & 3;
        #pragma unroll
        for (int q = 0; q < 4; q++)
            *(float4*)&Vt[m*16 + ((q ^ s) << 2)] = vsrc[q];
    }
    __syncthreads();

    float a0=0.f, a1=0.f, a2=0.f, a3=0.f;
    int mb = tz << 6;
    #pragma unroll 4
    for (int k = 0; k < 64; k++) {
        int m = mb + k;
        float a = At2[ty*256 + (m ^ ty)];
        float4 vv = *(const float4*)&Vt[m*16 + ((tx ^ ((m>>1)&3)) << 2)];
        a0 += a*vv.x; a1 += a*vv.y; a2 += a*vv.z; a3 += a*vv.w;
    }
    __syncthreads();                 // all Vt reads done before overlay
    float* part = Vt;                // reuse Vt as partial buffer (1024 floats)
    *(float4*)&part[t << 2] = make_float4(a0, a1, a2, a3);
    __syncthreads();
    if (tz == 0) {
        float4 r0 = *(const float4*)&part[(t      ) << 2];
        float4 r1 = *(const float4*)&part[(t + 64 ) << 2];
        float4 r2 = *(const float4*)&part[(t + 128) << 2];
        float4 r3 = *(const float4*)&part[(t + 192) << 2];
        float4 res = make_float4(r0.x+r1.x+r2.x+r3.x, r0.y+r1.y+r2.y+r3.y,
                                 r0.z+r1.z+r2.z+r3.z, r0.w+r1.w+r2.w+r3.w);
        *(float4*)(g_o1 + (size_t)(b*Nv + n0 + ty)*Dv + h*HDv + dh*16 + (tx<<2)) = res;
    }
}

// ---------------- K4: 8 rows/CTA: out-proj + gcn-proj + LN ----------------
__global__ __launch_bounds__(256) void k_final(const float* __restrict__ hin,
                                               const float* __restrict__ out_w,
                                               const float* __restrict__ out_b,
                                               const float* __restrict__ gcn_w,
                                               const float* __restrict__ gcn_b,
                                               const float* __restrict__ ln_g,
                                               const float* __restrict__ ln_b,
                                               float* __restrict__ out) {
    int bn0 = blockIdx.x << 3;
    int t = threadIdx.x;
    __shared__ float hs[8*Dv];
    __shared__ float os[8*Dv];
    __shared__ float hag[8*Dv];
    __shared__ float yb[8*Dv];
    __shared__ float gb[8*Dv];
    for (int i = t; i < 8*Dv; i += 256) {
        size_t gi = (size_t)bn0*Dv + i;
        os[i]  = g_o1[gi] + g_o2[gi];
        hag[i] = g_hagg[gi];
        hs[i]  = hin[gi];
    }
    __syncthreads();
    int grp = t >> 7, d = t & 127;
    {
        const float4* W4 = (const float4*)(grp ? gcn_w : out_w);
        float bias = grp ? gcn_b[d] : out_b[d];
        const float4* X4 = (const float4*)(grp ? hag : os);
        float* Y = grp ? gb : yb;
        float acc[8];
        #pragma unroll
        for (int r = 0; r < 8; r++) acc[r] = bias;
        #pragma unroll 4
        for (int j4 = 0; j4 < 32; j4++) {
            float4 w = W4[d*32 + j4];
            #pragma unroll
            for (int r = 0; r < 8; r++) {
                float4 hv = X4[r*32 + j4];
                acc[r] += w.x*hv.x + w.y*hv.y + w.z*hv.z + w.w*hv.w;
            }
        }
        #pragma unroll
        for (int r = 0; r < 8; r++) Y[r*Dv + d] = acc[r];
    }
    __syncthreads();
    int wid = t >> 5, lane = t & 31;
    const float4* hs4 = (const float4*)hs;
    const float4* yb4 = (const float4*)yb;
    const float4* gb4 = (const float4*)gb;
    const float4* lg4 = (const float4*)ln_g;
    const float4* lb4 = (const float4*)ln_b;
    {
        int r = wid;
        float4 a = hs4[r*32 + lane];
        float4 bq = yb4[r*32 + lane];
        float x0 = a.x + bq.x, x1 = a.y + bq.y, x2 = a.z + bq.z, x3 = a.w + bq.w;
        float s = x0 + x1 + x2 + x3;
        #pragma unroll
        for (int o = 16; o > 0; o >>= 1) s += __shfl_xor_sync(0xffffffffu, s, o);
        float mu = s * (1.0f/128.0f);
        float c0 = x0-mu, c1 = x1-mu, c2 = x2-mu, c3 = x3-mu;
        float vv = c0*c0 + c1*c1 + c2*c2 + c3*c3;
        #pragma unroll
        for (int o = 16; o > 0; o >>= 1) vv += __shfl_xor_sync(0xffffffffu, vv, o);
        float rs = rsqrtf(vv * (1.0f/128.0f) + 1e-5f);
        float4 g = lg4[lane], lb = lb4[lane], gg = gb4[r*32 + lane];
        float4 res;
        res.x = gg.x + g.x*c0*rs + lb.x;
        res.y = gg.y + g.y*c1*rs + lb.y;
        res.z = gg.z + g.z*c2*rs + lb.z;
        res.w = gg.w + g.w*c3*rs + lb.w;
        *(float4*)(out + (size_t)(bn0 + r)*Dv + lane*4) = res;
    }
}

extern "C" void kernel_launch(void* const* d_in, const int* in_sizes, int n_in,
                              void* d_out, int out_size) {
    const float* h     = (const float*)d_in[0];
    const float* adj   = (const float*)d_in[1];
    const float* ef    = (const float*)d_in[2];
    const float* smk   = (const float*)d_in[3];
    const float* gcn_w = (const float*)d_in[4];
    const float* gcn_b = (const float*)d_in[5];
    const float* edge_w= (const float*)d_in[6];
    const float* edge_b= (const float*)d_in[7];
    const float* wq    = (const float*)d_in[8];
    const float* wk    = (const float*)d_in[9];
    const float* wv    = (const float*)d_in[10];
    const float* bq    = (const float*)d_in[11];
    const float* bk    = (const float*)d_in[12];
    const float* bv    = (const float*)d_in[13];
    const float* out_w = (const float*)d_in[14];
    const float* out_b = (const float*)d_in[15];
    const float* ln_g  = (const float*)d_in[16];
    const float* ln_b  = (const float*)d_in[17];
    float* out = (float*)d_out;

    k_front<<<544, 384>>>(h, adj, wq, wk, wv, bq, bk, bv, edge_w, edge_b);
    k_s0   <<<dim3(Bv*Hv, 8, 4), 256>>>();
    k_att  <<<BN, 256>>>(ef, adj, smk);
    k_o1   <<<dim3(Bv*Hv, 16, 2), 256>>>();
    k_final<<<BN/8, 256>>>(h, out_w, out_b, gcn_w, gcn_b, ln_g, ln_b, out);
}

// round 8
// speedup vs baseline: 4.7291x; 1.1466x over previous
#include <cuda_runtime.h>

#define Bv 8
#define Nv 256
#define Dv 128
#define Ev 32
#define Hv 4
#define HDv 32
#define BN (Bv*Nv)

// ---------------- scratch (device globals; no allocation allowed) ----------------
__device__ float g_wke[Dv*Ev];
__device__ float g_wve[Dv*Ev];
__device__ float g_q  [BN*Dv];
__device__ float g_kh [BN*Dv];
__device__ float g_vh [BN*Dv];
__device__ float g_S0 [Bv*Hv*Nv*Nv];    // [b][h][n][m]
__device__ float g_o1 [BN*Dv];          // o1 + o2 (full attention output pre-proj)
__device__ float g_hagg[BN*Dv];

// ---------------- K0: fused front: proj (blk<256) | gcn (256..511) | prep (512..543) ----
__global__ __launch_bounds__(384) void k_front(const float* __restrict__ hin,
                                               const float* __restrict__ adj,
                                               const float* __restrict__ wq,
                                               const float* __restrict__ wk,
                                               const float* __restrict__ wv,
                                               const float* __restrict__ bq,
                                               const float* __restrict__ bk,
                                               const float* __restrict__ bv,
                                               const float* __restrict__ edge_w,
                                               const float* __restrict__ edge_b) {
    int blk = blockIdx.x, t = threadIdx.x;
    if (blk < 256) {
        __shared__ float hs[9*Dv];
        int bn0 = blk << 3;
        for (int i = t; i < 9*Dv; i += 384)
            hs[i] = (i < 8*Dv) ? hin[(size_t)bn0*Dv + i] : edge_b[i - 8*Dv];
        __syncthreads();
        int mat = t >> 7, d = t & 127;
        const float* W = (mat == 0) ? wq : (mat == 1) ? wk : wv;
        float bias = (mat == 0) ? bq[d] : (mat == 1) ? bk[d] : bv[d];
        float acc[9];
        #pragma unroll
        for (int r = 0; r < 9; r++) acc[r] = 0.f;
        const float4* W4 = (const float4*)W;
        const float4* hs4 = (const float4*)hs;
        #pragma unroll 4
        for (int j4 = 0; j4 < 32; j4++) {
            float4 w = W4[d*32 + j4];
            #pragma unroll
            for (int r = 0; r < 9; r++) {
                float4 hv = hs4[r*32 + j4];
                acc[r] += w.x*hv.x + w.y*hv.y + w.z*hv.z + w.w*hv.w;
            }
        }
        float* dst = (mat == 0) ? g_q : (mat == 1) ? g_kh : g_vh;
        float cadd = (mat == 0) ? bias : (bias + acc[8]);
        #pragma unroll
        for (int r = 0; r < 8; r++)
            dst[(size_t)(bn0 + r)*Dv + d] = acc[r] + cadd;
    } else if (blk < 512) {
        __shared__ float adjs[8*Nv];
        __shared__ float part[3*8*Dv];
        __shared__ float degs[8];
        int g = blk - 256; int b = g >> 5; int n0 = (g & 31) << 3;
        for (int i = t; i < 8*Nv; i += 384) {
            int r = i >> 8, m = i & 255;
            adjs[i] = adj[((size_t)b*Nv + (n0+r))*Nv + m];
        }
        __syncthreads();
        if (t < 8) adjs[t*Nv + n0 + t] += 1.0f;
        __syncthreads();
        if (t < 128) {
            int r = t >> 4, lane = t & 15;
            float p = 0.f;
            #pragma unroll
            for (int k = 0; k < 16; k++) p += adjs[r*Nv + lane*16 + k];
            #pragma unroll
            for (int o = 8; o > 0; o >>= 1) p += __shfl_xor_sync(0xffffffffu, p, o, 16);
            if (lane == 0) degs[r] = p;
        }
        __syncthreads();
        int grp = t >> 7, d = t & 127;
        const int mlo = (grp == 0) ? 0 : (grp == 1) ? 86 : 171;
        const int mhi = (grp == 0) ? 86 : (grp == 1) ? 171 : 256;
        float acc[8];
        #pragma unroll
        for (int r = 0; r < 8; r++) acc[r] = 0.f;
        for (int m = mlo; m < mhi; m++) {
            float hv = hin[((size_t)b*Nv + m)*Dv + d];
            #pragma unroll
            for (int r = 0; r < 8; r++) acc[r] += adjs[r*Nv + m] * hv;
        }
        #pragma unroll
        for (int r = 0; r < 8; r++) part[grp*8*Dv + r*Dv + d] = acc[r];
        __syncthreads();
        if (t < 128) {
            #pragma unroll
            for (int r = 0; r < 8; r++) {
                float s = part[0*8*Dv + r*Dv + t] + part[1*8*Dv + r*Dv + t] + part[2*8*Dv + r*Dv + t];
                g_hagg[((size_t)b*Nv + n0 + r)*Dv + t] = s / degs[r];
            }
        }
    } else {
        if (t < 128) {
            int pb = blk - 512;
            int dl = t >> 5, e = t & 31;
            int d = pb * 4 + dl;
            float sk = 0.f, sv = 0.f;
            #pragma unroll 8
            for (int j = 0; j < Dv; j++) {
                float ew = edge_w[j*Ev + e];
                sk += wk[d*Dv + j] * ew;
                sv += wv[d*Dv + j] * ew;
            }
            g_wke[d*Ev + e] = sk;
            g_wve[d*Ev + e] = sv;
        }
    }
}

// ---------------- K1: S0 = Q_h K_h^T (32x64 tiles, grid 1024) ----------------
__global__ __launch_bounds__(256) void k_s0() {
    int bh = blockIdx.x; int b = bh >> 2, h = bh & 3;
    int n0 = blockIdx.y << 5, m0 = blockIdx.z << 6;
    __shared__ float Qt[32*33];
    __shared__ float Kt[64*33];
    int t = threadIdx.x;
    {
        int r = t >> 3, c4 = (t & 7) << 2;
        float4 w0 = *(const float4*)(g_kh + ((size_t)(b*Nv + m0 + r))*Dv + h*HDv + c4);
        float* q0 = &Kt[r*33 + c4];
        q0[0]=w0.x; q0[1]=w0.y; q0[2]=w0.z; q0[3]=w0.w;
        float4 w1 = *(const float4*)(g_kh + ((size_t)(b*Nv + m0 + 32 + r))*Dv + h*HDv + c4);
        float* q1 = &Kt[(32+r)*33 + c4];
        q1[0]=w1.x; q1[1]=w1.y; q1[2]=w1.z; q1[3]=w1.w;
        if (r < 32) {
            float4 v = *(const float4*)(g_q + ((size_t)(b*Nv + n0 + r))*Dv + h*HDv + c4);
            float* p = &Qt[r*33 + c4];
            p[0]=v.x; p[1]=v.y; p[2]=v.z; p[3]=v.w;
        }
    }
    __syncthreads();
    int tx = t & 15, ty = t >> 4;
    float acc[2][4];
    #pragma unroll
    for (int i = 0; i < 2; i++)
        #pragma unroll
        for (int j = 0; j < 4; j++) acc[i][j] = 0.f;
    #pragma unroll 4
    for (int e = 0; e < HDv; e++) {
        float qr[2], kr[4];
        qr[0] = Qt[(ty*2+0)*33 + e];
        qr[1] = Qt[(ty*2+1)*33 + e];
        #pragma unroll
        for (int j = 0; j < 4; j++) kr[j] = Kt[(tx*4+j)*33 + e];
        #pragma unroll
        for (int i = 0; i < 2; i++)
            #pragma unroll
            for (int j = 0; j < 4; j++) acc[i][j] += qr[i]*kr[j];
    }
    float* dst = g_S0 + (size_t)(b*Hv + h)*Nv*Nv;
    #pragma unroll
    for (int i = 0; i < 2; i++) {
        float* p = dst + (size_t)(n0 + ty*2 + i)*Nv + m0 + tx*4;
        *(float4*)p = make_float4(acc[i][0],acc[i][1],acc[i][2],acc[i][3]);
    }
}

// ---------------- K2: single-pass attention: scores + exp + o1 + ae + o2 -----------
// CTA = 8 n-rows (warp per row), 256 CTAs. Warp-private smem slices -> __syncwarp only.
__global__ __launch_bounds__(256) void k_att2(const float* __restrict__ ef,
                                              const float* __restrict__ adj,
                                              const float* __restrict__ srcm) {
    int blk = blockIdx.x; int b = blk >> 5; int n0 = (blk & 31) << 3;
    __shared__ float sm[11264];            // 44 KB
    float* s_qrow = sm;                    // [8][128]   (later: aes [8][4][32])
    float* s_qks  = sm + 1024;             // [8][128]
    float* s_efs  = sm + 2048;             // [8][32][32] rotated (later: wvet [32][128])
    float* s_exch = sm + 10240;            // [8][32] float4 (exp per head)

    int t = threadIdx.x;
    int n = t >> 5;                        // warp = n-row
    int x = t & 31;                        // lane
    int bn = b*Nv + n0 + n;

    // stage q row (warp-local)
    *(float4*)&s_qrow[t*4] = *(const float4*)(g_q + ((size_t)(b*Nv + n0))*Dv + t*4);
    __syncwarp();
    // qk_e: qks[n][h*32+e] = sum_j q[n][h*32+j] * wke[(h*32+j)*32+e]
    #pragma unroll
    for (int h = 0; h < 4; h++) {
        float s = 0.f;
        #pragma unroll 8
        for (int j = 0; j < 32; j++)
            s += s_qrow[n*128 + h*32 + j] * g_wke[(h*32 + j)*Ev + x];
        s_qks[n*128 + h*32 + x] = s;
    }
    __syncwarp();

    const float SCALE = 0.17677669529663687f;   // 1/sqrt(32)
    float4 o1a = make_float4(0.f,0.f,0.f,0.f);
    float den1 = 0.f;
    float4 den4 = make_float4(0.f,0.f,0.f,0.f);
    float ae0=0.f, ae1=0.f, ae2=0.f, ae3=0.f;
    int ho = x >> 3;                       // head for o1/o2 (d-quad x -> d=4x)

    for (int mc = 0; mc < Nv; mc += 32) {
        int m = mc + x;
        // ---- front-loaded global reads ----
        float4 f[8];
        const float4* efsrc = (const float4*)(ef + ((size_t)bn*Nv + m)*Ev);
        #pragma unroll
        for (int i = 0; i < 8; i++) f[i] = efsrc[i];
        float wmask = adj[(size_t)bn*Nv + m] * srcm[(size_t)bn*Nv + m];
        float s00 = g_S0[((size_t)(b*Hv+0)*Nv + (n0+n))*Nv + m];
        float s01 = g_S0[((size_t)(b*Hv+1)*Nv + (n0+n))*Nv + m];
        float s02 = g_S0[((size_t)(b*Hv+2)*Nv + (n0+n))*Nv + m];
        float s03 = g_S0[((size_t)(b*Hv+3)*Nv + (n0+n))*Nv + m];
        // ---- stage ef to smem, rotation swizzle (bank = (e+x)&31, conflict-free) ----
        {
            float* dst = &s_efs[(n*32 + x)*32];
            const float* ff = (const float*)f;
            #pragma unroll
            for (int e = 0; e < 32; e++)
                dst[(e + x) & 31] = ff[e];
        }
        // ---- scores from registers + qks broadcasts ----
        float es0=0.f, es1=0.f, es2=0.f, es3=0.f;
        #pragma unroll
        for (int e4 = 0; e4 < 8; e4++) {
            float4 fe = f[e4];
            float4 q0 = *(const float4*)&s_qks[n*128 + 0*32 + e4*4];
            float4 q1 = *(const float4*)&s_qks[n*128 + 1*32 + e4*4];
            float4 q2 = *(const float4*)&s_qks[n*128 + 2*32 + e4*4];
            float4 q3 = *(const float4*)&s_qks[n*128 + 3*32 + e4*4];
            es0 += fe.x*q0.x + fe.y*q0.y + fe.z*q0.z + fe.w*q0.w;
            es1 += fe.x*q1.x + fe.y*q1.y + fe.z*q1.z + fe.w*q1.w;
            es2 += fe.x*q2.x + fe.y*q2.y + fe.z*q2.z + fe.w*q2.w;
            es3 += fe.x*q3.x + fe.y*q3.y + fe.z*q3.z + fe.w*q3.w;
        }
        float4 exv;
        if (wmask == 0.0f) {
            exv = make_float4(0.f,0.f,0.f,0.f);
        } else {
            exv.x = __expf((s00+es0)*SCALE);
            exv.y = __expf((s01+es1)*SCALE);
            exv.z = __expf((s02+es2)*SCALE);
            exv.w = __expf((s03+es3)*SCALE);
        }
        *(float4*)&s_exch[t*4] = exv;
        __syncwarp();

        // ---- o1 accumulate: v from global (L1-hot), exp multicast from smem ----
        const float* vbase = g_vh + ((size_t)(b*Nv + mc))*Dv;
        #pragma unroll 4
        for (int mm = 0; mm < 32; mm++) {
            float exm = s_exch[(n*32+mm)*4 + ho];
            float4 vv = *(const float4*)(vbase + (size_t)mm*Dv + x*4);
            o1a.x += exm*vv.x; o1a.y += exm*vv.y; o1a.z += exm*vv.z; o1a.w += exm*vv.w;
            den1 += exm;
        }
        // ---- ae accumulate: ef from rotated smem, exp4 broadcast ----
        #pragma unroll 4
        for (int mm = 0; mm < 32; mm++) {
            float4 e4 = *(const float4*)&s_exch[(n*32+mm)*4];
            float fv = s_efs[(n*32+mm)*32 + ((x+mm)&31)];
            ae0 += e4.x*fv; ae1 += e4.y*fv; ae2 += e4.z*fv; ae3 += e4.w*fv;
            den4.x += e4.x; den4.y += e4.y; den4.z += e4.z; den4.w += e4.w;
        }
        __syncwarp();
    }

    // normalize ae -> aes (reuse s_qrow)
    {
        float* aes = s_qrow;
        aes[(n*4+0)*32 + x] = ae0 / den4.x;
        aes[(n*4+1)*32 + x] = ae1 / den4.y;
        aes[(n*4+2)*32 + x] = ae2 / den4.z;
        aes[(n*4+3)*32 + x] = ae3 / den4.w;
    }
    __syncthreads();               // all warps done with their efs slices
    // stage wve^T (32e x 128d) into s_efs
    #pragma unroll
    for (int i = 0; i < 16; i++) {
        int idx = i*256 + t;
        int e = idx >> 7, d = idx & 127;
        s_efs[e*128 + d] = g_wve[d*Ev + e];
    }
    __syncthreads();
    // o2 + final write: thread (n, d-quad x), head ho
    {
        float inv = 1.0f / den1;
        float4 res = make_float4(o1a.x*inv, o1a.y*inv, o1a.z*inv, o1a.w*inv);
        const float* aes = s_qrow + (n*4 + ho)*32;
        #pragma unroll 8
        for (int e = 0; e < 32; e++) {
            float a = aes[e];
            float4 wv = *(const float4*)&s_efs[e*128 + x*4];
            res.x += a*wv.x; res.y += a*wv.y; res.z += a*wv.z; res.w += a*wv.w;
        }
        *(float4*)(g_o1 + ((size_t)bn)*Dv + x*4) = res;
    }
}

// ---------------- K3: 8 rows/CTA: out-proj + gcn-proj + LN ----------------
__global__ __launch_bounds__(256) void k_final(const float* __restrict__ hin,
                                               const float* __restrict__ out_w,
                                               const float* __restrict__ out_b,
                                               const float* __restrict__ gcn_w,
                                               const float* __restrict__ gcn_b,
                                               const float* __restrict__ ln_g,
                                               const float* __restrict__ ln_b,
                                               float* __restrict__ out) {
    int bn0 = blockIdx.x << 3;
    int t = threadIdx.x;
    __shared__ float hs[8*Dv];
    __shared__ float os[8*Dv];
    __shared__ float hag[8*Dv];
    __shared__ float yb[8*Dv];
    __shared__ float gb[8*Dv];
    for (int i = t; i < 8*Dv; i += 256) {
        size_t gi = (size_t)bn0*Dv + i;
        os[i]  = g_o1[gi];
        hag[i] = g_hagg[gi];
        hs[i]  = hin[gi];
    }
    __syncthreads();
    int grp = t >> 7, d = t & 127;
    {
        const float4* W4 = (const float4*)(grp ? gcn_w : out_w);
        float bias = grp ? gcn_b[d] : out_b[d];
        const float4* X4 = (const float4*)(grp ? hag : os);
        float* Y = grp ? gb : yb;
        float acc[8];
        #pragma unroll
        for (int r = 0; r < 8; r++) acc[r] = bias;
        #pragma unroll 4
        for (int j4 = 0; j4 < 32; j4++) {
            float4 w = W4[d*32 + j4];
            #pragma unroll
            for (int r = 0; r < 8; r++) {
                float4 hv = X4[r*32 + j4];
                acc[r] += w.x*hv.x + w.y*hv.y + w.z*hv.z + w.w*hv.w;
            }
        }
        #pragma unroll
        for (int r = 0; r < 8; r++) Y[r*Dv + d] = acc[r];
    }
    __syncthreads();
    int wid = t >> 5, lane = t & 31;
    const float4* hs4 = (const float4*)hs;
    const float4* yb4 = (const float4*)yb;
    const float4* gb4 = (const float4*)gb;
    const float4* lg4 = (const float4*)ln_g;
    const float4* lb4 = (const float4*)ln_b;
    {
        int r = wid;
        float4 a = hs4[r*32 + lane];
        float4 bq = yb4[r*32 + lane];
        float x0 = a.x + bq.x, x1 = a.y + bq.y, x2 = a.z + bq.z, x3 = a.w + bq.w;
        float s = x0 + x1 + x2 + x3;
        #pragma unroll
        for (int o = 16; o > 0; o >>= 1) s += __shfl_xor_sync(0xffffffffu, s, o);
        float mu = s * (1.0f/128.0f);
        float c0 = x0-mu, c1 = x1-mu, c2 = x2-mu, c3 = x3-mu;
        float vv = c0*c0 + c1*c1 + c2*c2 + c3*c3;
        #pragma unroll
        for (int o = 16; o > 0; o >>= 1) vv += __shfl_xor_sync(0xffffffffu, vv, o);
        float rs = rsqrtf(vv * (1.0f/128.0f) + 1e-5f);
        float4 g = lg4[lane], lb = lb4[lane], gg = gb4[r*32 + lane];
        float4 res;
        res.x = gg.x + g.x*c0*rs + lb.x;
        res.y = gg.y + g.y*c1*rs + lb.y;
        res.z = gg.z + g.z*c2*rs + lb.z;
        res.w = gg.w + g.w*c3*rs + lb.w;
        *(float4*)(out + (size_t)(bn0 + r)*Dv + lane*4) = res;
    }
}

extern "C" void kernel_launch(void* const* d_in, const int* in_sizes, int n_in,
                              void* d_out, int out_size) {
    const float* h     = (const float*)d_in[0];
    const float* adj   = (const float*)d_in[1];
    const float* ef    = (const float*)d_in[2];
    const float* smk   = (const float*)d_in[3];
    const float* gcn_w = (const float*)d_in[4];
    const float* gcn_b = (const float*)d_in[5];
    const float* edge_w= (const float*)d_in[6];
    const float* edge_b= (const float*)d_in[7];
    const float* wq    = (const float*)d_in[8];
    const float* wk    = (const float*)d_in[9];
    const float* wv    = (const float*)d_in[10];
    const float* bq    = (const float*)d_in[11];
    const float* bk    = (const float*)d_in[12];
    const float* bv    = (const float*)d_in[13];
    const float* out_w = (const float*)d_in[14];
    const float* out_b = (const float*)d_in[15];
    const float* ln_g  = (const float*)d_in[16];
    const float* ln_b  = (const float*)d_in[17];
    float* out = (float*)d_out;

    k_front<<<544, 384>>>(h, adj, wq, wk, wv, bq, bk, bv, edge_w, edge_b);
    k_s0   <<<dim3(Bv*Hv, 8, 4), 256>>>();
    k_att2 <<<256, 256>>>(ef, adj, smk);
    k_final<<<BN/8, 256>>>(h, out_w, out_b, gcn_w, gcn_b, ln_g, ln_b, out);
}